// round 1
// baseline (speedup 1.0000x reference)
#include <cuda_runtime.h>
#include <math.h>

#define D_MODEL 1024
#define N_HEADS 16
#define D_HEAD  64
#define B_SZ    4
#define T_SEQ   2048
#define M_ROWS  (B_SZ * T_SEQ)   // 8192

// Scratch (allocation-free rule: __device__ globals)
__device__ float g_Q[M_ROWS * D_MODEL];
__device__ float g_K[M_ROWS * D_MODEL];
__device__ float g_V[M_ROWS * D_MODEL];
__device__ float g_O[M_ROWS * D_MODEL];

// ---------------------------------------------------------------------------
// Generic GEMM: C[M,N] = A[M,K] @ W[N,K]^T + bias[N]
// 128x128 block tile, BK=16, 256 threads, 8x8 per-thread register tile.
// ---------------------------------------------------------------------------
__global__ __launch_bounds__(256, 2)
void gemm_bias_kernel(const float* __restrict__ A,
                      const float* __restrict__ W,
                      const float* __restrict__ bias,
                      float* __restrict__ C,
                      int M, int N, int K)
{
    __shared__ float As[16][128];
    __shared__ float Bs[16][128];

    const int tid = threadIdx.x;
    const int m0 = blockIdx.y * 128;
    const int n0 = blockIdx.x * 128;
    const int rowBase = (tid >> 4) * 8;   // 0..120
    const int colBase = (tid & 15) * 8;   // 0..120

    float acc[8][8];
#pragma unroll
    for (int i = 0; i < 8; i++)
#pragma unroll
        for (int j = 0; j < 8; j++) acc[i][j] = 0.f;

    for (int k0 = 0; k0 < K; k0 += 16) {
        // Load A and W tiles (transposed into smem: [k][m] / [k][n])
#pragma unroll
        for (int l = 0; l < 2; l++) {
            int fid = tid + l * 256;          // 0..511
            int r   = fid >> 2;               // 0..127
            int c4  = (fid & 3) * 4;          // 0,4,8,12
            float4 va = *reinterpret_cast<const float4*>(&A[(m0 + r) * K + k0 + c4]);
            As[c4 + 0][r] = va.x; As[c4 + 1][r] = va.y;
            As[c4 + 2][r] = va.z; As[c4 + 3][r] = va.w;
            float4 vb = *reinterpret_cast<const float4*>(&W[(n0 + r) * K + k0 + c4]);
            Bs[c4 + 0][r] = vb.x; Bs[c4 + 1][r] = vb.y;
            Bs[c4 + 2][r] = vb.z; Bs[c4 + 3][r] = vb.w;
        }
        __syncthreads();

#pragma unroll
        for (int k = 0; k < 16; k++) {
            float a[8], b[8];
#pragma unroll
            for (int i = 0; i < 8; i += 4) {
                float4 v = *reinterpret_cast<const float4*>(&As[k][rowBase + i]);
                a[i] = v.x; a[i + 1] = v.y; a[i + 2] = v.z; a[i + 3] = v.w;
            }
#pragma unroll
            for (int j = 0; j < 8; j += 4) {
                float4 v = *reinterpret_cast<const float4*>(&Bs[k][colBase + j]);
                b[j] = v.x; b[j + 1] = v.y; b[j + 2] = v.z; b[j + 3] = v.w;
            }
#pragma unroll
            for (int i = 0; i < 8; i++)
#pragma unroll
                for (int j = 0; j < 8; j++)
                    acc[i][j] = fmaf(a[i], b[j], acc[i][j]);
        }
        __syncthreads();
    }

    // Epilogue with bias
    float bj[8];
#pragma unroll
    for (int j = 0; j < 8; j += 4) {
        float4 v = *reinterpret_cast<const float4*>(&bias[n0 + colBase + j]);
        bj[j] = v.x; bj[j + 1] = v.y; bj[j + 2] = v.z; bj[j + 3] = v.w;
    }
#pragma unroll
    for (int i = 0; i < 8; i++) {
#pragma unroll
        for (int j = 0; j < 8; j += 4) {
            float4 o;
            o.x = acc[i][j + 0] + bj[j + 0];
            o.y = acc[i][j + 1] + bj[j + 1];
            o.z = acc[i][j + 2] + bj[j + 2];
            o.w = acc[i][j + 3] + bj[j + 3];
            *reinterpret_cast<float4*>(&C[(m0 + rowBase + i) * N + n0 + colBase + j]) = o;
        }
    }
}

// ---------------------------------------------------------------------------
// Causal flash attention, fp32. 64x64 tiles, D_HEAD=64.
// Grid: (T/64 q-tiles, B*H). 128 threads: 16x8 layout, each thread 4 rows x 8 cols.
// Q/K/V read from [8192,1024] buffers at head offset; output written as
// [B, T, H*D] = [8192, 1024] so the final projection is a plain GEMM.
// ---------------------------------------------------------------------------
#define FPAD 68

__global__ __launch_bounds__(128)
void flash_kernel(const float* __restrict__ Q,
                  const float* __restrict__ K,
                  const float* __restrict__ V,
                  float* __restrict__ O)
{
    extern __shared__ float sm[];
    float* Qs = sm;                 // 64 * FPAD
    float* Ks = Qs + 64 * FPAD;
    float* Vs = Ks + 64 * FPAD;
    float* Ps = Vs + 64 * FPAD;

    const int tid = threadIdx.x;
    const int ty = tid >> 3;        // 0..15
    const int tx = tid & 7;         // 0..7
    const int r0 = ty * 4;
    const int c0 = tx * 8;

    const int qtile = blockIdx.x;
    const int bh = blockIdx.y;
    const int b = bh >> 4;
    const int h = bh & 15;
    const int rowbase = b * T_SEQ;
    const int hoff = h * D_HEAD;
    const int qb = qtile * 64;

    // Load Q tile (64 rows x 64 cols)
#pragma unroll
    for (int l = 0; l < 8; l++) {
        int fid = tid + l * 128;      // 0..1023
        int rr = fid >> 4;
        int cc = (fid & 15) * 4;
        *reinterpret_cast<float4*>(&Qs[rr * FPAD + cc]) =
            *reinterpret_cast<const float4*>(&Q[(rowbase + qb + rr) * D_MODEL + hoff + cc]);
    }

    float mrow[4], lrow[4], o[4][8];
#pragma unroll
    for (int i = 0; i < 4; i++) {
        mrow[i] = -INFINITY;
        lrow[i] = 0.f;
#pragma unroll
        for (int j = 0; j < 8; j++) o[i][j] = 0.f;
    }

    for (int kt = 0; kt <= qtile; kt++) {
        const int kb = kt * 64;
        // Load K, V tiles
#pragma unroll
        for (int l = 0; l < 8; l++) {
            int fid = tid + l * 128;
            int rr = fid >> 4;
            int cc = (fid & 15) * 4;
            *reinterpret_cast<float4*>(&Ks[rr * FPAD + cc]) =
                *reinterpret_cast<const float4*>(&K[(rowbase + kb + rr) * D_MODEL + hoff + cc]);
            *reinterpret_cast<float4*>(&Vs[rr * FPAD + cc]) =
                *reinterpret_cast<const float4*>(&V[(rowbase + kb + rr) * D_MODEL + hoff + cc]);
        }
        __syncthreads();

        // S = Q @ K^T for this thread's 4x8 sub-tile
        float s[4][8];
#pragma unroll
        for (int i = 0; i < 4; i++)
#pragma unroll
            for (int j = 0; j < 8; j++) s[i][j] = 0.f;

        for (int d = 0; d < 64; d += 4) {
            float4 qv[4], kv[8];
#pragma unroll
            for (int i = 0; i < 4; i++)
                qv[i] = *reinterpret_cast<const float4*>(&Qs[(r0 + i) * FPAD + d]);
#pragma unroll
            for (int j = 0; j < 8; j++)
                kv[j] = *reinterpret_cast<const float4*>(&Ks[(c0 + j) * FPAD + d]);
#pragma unroll
            for (int i = 0; i < 4; i++)
#pragma unroll
                for (int j = 0; j < 8; j++) {
                    s[i][j] = fmaf(qv[i].x, kv[j].x, s[i][j]);
                    s[i][j] = fmaf(qv[i].y, kv[j].y, s[i][j]);
                    s[i][j] = fmaf(qv[i].z, kv[j].z, s[i][j]);
                    s[i][j] = fmaf(qv[i].w, kv[j].w, s[i][j]);
                }
        }

        const bool diag = (kt == qtile);
#pragma unroll
        for (int i = 0; i < 4; i++) {
#pragma unroll
            for (int j = 0; j < 8; j++) {
                s[i][j] *= 0.125f;   // 1/sqrt(64)
                if (diag && (c0 + j > r0 + i)) s[i][j] = -INFINITY;
            }
        }

        // Online softmax (row reductions across the 8-lane tx group)
#pragma unroll
        for (int i = 0; i < 4; i++) {
            float rm = s[i][0];
#pragma unroll
            for (int j = 1; j < 8; j++) rm = fmaxf(rm, s[i][j]);
            rm = fmaxf(rm, __shfl_xor_sync(0xffffffffu, rm, 1));
            rm = fmaxf(rm, __shfl_xor_sync(0xffffffffu, rm, 2));
            rm = fmaxf(rm, __shfl_xor_sync(0xffffffffu, rm, 4));

            float mn = fmaxf(mrow[i], rm);
            float corr = __expf(mrow[i] - mn);
            float rs = 0.f;
#pragma unroll
            for (int j = 0; j < 8; j++) {
                s[i][j] = __expf(s[i][j] - mn);
                rs += s[i][j];
            }
            rs += __shfl_xor_sync(0xffffffffu, rs, 1);
            rs += __shfl_xor_sync(0xffffffffu, rs, 2);
            rs += __shfl_xor_sync(0xffffffffu, rs, 4);

            lrow[i] = lrow[i] * corr + rs;
            mrow[i] = mn;
#pragma unroll
            for (int j = 0; j < 8; j++) o[i][j] *= corr;
        }

        // Write P to smem
#pragma unroll
        for (int i = 0; i < 4; i++) {
            float4 p0 = make_float4(s[i][0], s[i][1], s[i][2], s[i][3]);
            float4 p1 = make_float4(s[i][4], s[i][5], s[i][6], s[i][7]);
            *reinterpret_cast<float4*>(&Ps[(r0 + i) * FPAD + c0 + 0]) = p0;
            *reinterpret_cast<float4*>(&Ps[(r0 + i) * FPAD + c0 + 4]) = p1;
        }
        __syncthreads();

        // O += P @ V  (this thread owns rows r0..r0+3, d-cols c0..c0+7)
        for (int c = 0; c < 64; c += 4) {
            float4 pv[4];
#pragma unroll
            for (int i = 0; i < 4; i++)
                pv[i] = *reinterpret_cast<const float4*>(&Ps[(r0 + i) * FPAD + c]);
#pragma unroll
            for (int cc = 0; cc < 4; cc++) {
                float4 va = *reinterpret_cast<const float4*>(&Vs[(c + cc) * FPAD + c0 + 0]);
                float4 vb = *reinterpret_cast<const float4*>(&Vs[(c + cc) * FPAD + c0 + 4]);
#pragma unroll
                for (int i = 0; i < 4; i++) {
                    float p = (cc == 0) ? pv[i].x : (cc == 1) ? pv[i].y
                             : (cc == 2) ? pv[i].z : pv[i].w;
                    o[i][0] = fmaf(p, va.x, o[i][0]);
                    o[i][1] = fmaf(p, va.y, o[i][1]);
                    o[i][2] = fmaf(p, va.z, o[i][2]);
                    o[i][3] = fmaf(p, va.w, o[i][3]);
                    o[i][4] = fmaf(p, vb.x, o[i][4]);
                    o[i][5] = fmaf(p, vb.y, o[i][5]);
                    o[i][6] = fmaf(p, vb.z, o[i][6]);
                    o[i][7] = fmaf(p, vb.w, o[i][7]);
                }
            }
        }
        __syncthreads();
    }

    // Finalize and store: out layout [B, T, H*D]
#pragma unroll
    for (int i = 0; i < 4; i++) {
        float inv = 1.0f / lrow[i];
        float4 o0 = make_float4(o[i][0] * inv, o[i][1] * inv, o[i][2] * inv, o[i][3] * inv);
        float4 o1 = make_float4(o[i][4] * inv, o[i][5] * inv, o[i][6] * inv, o[i][7] * inv);
        int row = rowbase + qb + r0 + i;
        *reinterpret_cast<float4*>(&O[row * D_MODEL + hoff + c0 + 0]) = o0;
        *reinterpret_cast<float4*>(&O[row * D_MODEL + hoff + c0 + 4]) = o1;
    }
}

// ---------------------------------------------------------------------------
// Launch
// ---------------------------------------------------------------------------
extern "C" void kernel_launch(void* const* d_in, const int* in_sizes, int n_in,
                              void* d_out, int out_size)
{
    const float* x  = (const float*)d_in[0];
    const float* Wq = (const float*)d_in[1];
    const float* bq = (const float*)d_in[2];
    const float* Wk = (const float*)d_in[3];
    const float* bk = (const float*)d_in[4];
    const float* Wv = (const float*)d_in[5];
    const float* bv = (const float*)d_in[6];
    const float* Wo = (const float*)d_in[7];
    const float* bo = (const float*)d_in[8];
    float* out = (float*)d_out;

    float *Qb, *Kb, *Vb, *Ob;
    cudaGetSymbolAddress((void**)&Qb, g_Q);
    cudaGetSymbolAddress((void**)&Kb, g_K);
    cudaGetSymbolAddress((void**)&Vb, g_V);
    cudaGetSymbolAddress((void**)&Ob, g_O);

    dim3 gblock(256);
    dim3 ggrid(D_MODEL / 128, M_ROWS / 128);   // (8, 64)

    gemm_bias_kernel<<<ggrid, gblock>>>(x, Wq, bq, Qb, M_ROWS, D_MODEL, D_MODEL);
    gemm_bias_kernel<<<ggrid, gblock>>>(x, Wk, bk, Kb, M_ROWS, D_MODEL, D_MODEL);
    gemm_bias_kernel<<<ggrid, gblock>>>(x, Wv, bv, Vb, M_ROWS, D_MODEL, D_MODEL);

    int smem = 4 * 64 * FPAD * sizeof(float);  // 69632 B
    cudaFuncSetAttribute(flash_kernel, cudaFuncAttributeMaxDynamicSharedMemorySize, smem);
    dim3 fgrid(T_SEQ / 64, B_SZ * N_HEADS);    // (32, 64)
    flash_kernel<<<fgrid, 128, smem>>>(Qb, Kb, Vb, Ob);

    gemm_bias_kernel<<<ggrid, gblock>>>(Ob, Wo, bo, out, M_ROWS, D_MODEL, D_MODEL);
}

// round 2
// speedup vs baseline: 2.2507x; 2.2507x over previous
#include <cuda_runtime.h>
#include <math.h>

#define D_MODEL 1024
#define N_HEADS 16
#define D_HEAD  64
#define B_SZ    4
#define T_SEQ   2048
#define M_ROWS  (B_SZ * T_SEQ)   // 8192

// Scratch (allocation-free rule: __device__ globals)
__device__ float g_Q[M_ROWS * D_MODEL];
__device__ float g_K[M_ROWS * D_MODEL];
__device__ float g_V[M_ROWS * D_MODEL];
__device__ float g_O[M_ROWS * D_MODEL];

// ---------------------------------------------------------------------------
// helpers
// ---------------------------------------------------------------------------
__device__ __forceinline__ unsigned f2tf32(float x) {
    unsigned u;
    asm("cvt.rna.tf32.f32 %0, %1;" : "=r"(u) : "f"(x));
    return u;
}
__device__ __forceinline__ float tf32r(float x) { return __uint_as_float(f2tf32(x)); }

__device__ __forceinline__ float ex2f(float x) {
    float y;
    asm("ex2.approx.f32 %0, %1;" : "=f"(y) : "f"(x));
    return y;
}

// D(16x8,f32) += A(16x8,tf32,row) * B(8x8,tf32,col)
__device__ __forceinline__ void mma8(float c[4], const unsigned a[4], unsigned b0, unsigned b1) {
    asm("mma.sync.aligned.m16n8k8.row.col.f32.tf32.tf32.f32 "
        "{%0,%1,%2,%3}, {%4,%5,%6,%7}, {%8,%9}, {%0,%1,%2,%3};"
        : "+f"(c[0]), "+f"(c[1]), "+f"(c[2]), "+f"(c[3])
        : "r"(a[0]), "r"(a[1]), "r"(a[2]), "r"(a[3]), "r"(b0), "r"(b1));
}

// ---------------------------------------------------------------------------
// GEMM (tf32x2, 3-mma split): C[M,N] = A[M,K] @ W[N,K]^T + bias
// Block 128x128, BK=16, 256 threads (8 warps, 4x2), warp tile 32x64.
// smem holds hi/lo tf32 splits in fragment-major layout.
// ---------------------------------------------------------------------------
__global__ __launch_bounds__(256, 2)
void gemm_tf32x2(const float* __restrict__ A, const float* __restrict__ W,
                 const float* __restrict__ bias, float* __restrict__ C,
                 int M, int N, int K)
{
    __shared__ float sm[8192];     // 32KB: AH[2048] AL[2048] BH[2048] BL[2048]
    const int AH = 0, AL = 2048, BH = 4096, BL = 6144;

    const int tid  = threadIdx.x;
    const int lane = tid & 31;
    const int warp = tid >> 5;
    const int g = lane >> 2, t = lane & 3;
    const int wm = warp >> 1, wn = warp & 1;
    const int m0 = blockIdx.y * 128, n0 = blockIdx.x * 128;

    float c[2][8][4];
#pragma unroll
    for (int i = 0; i < 2; i++)
#pragma unroll
        for (int j = 0; j < 8; j++)
#pragma unroll
            for (int e = 0; e < 4; e++) c[i][j][e] = 0.f;

    for (int k0 = 0; k0 < K; k0 += 16) {
        // ---- stage + split + scatter to fragment-major layout ----
#pragma unroll
        for (int hh = 0; hh < 2; hh++) {
            int fid = tid + hh * 256;          // 0..511
            int r   = fid >> 2;                // 0..127
            int c4  = (fid & 3) * 4;           // 0,4,8,12

            float4 va = *reinterpret_cast<const float4*>(&A[(size_t)(m0 + r) * K + k0 + c4]);
            int mt = r >> 4, rm = r & 15;
            int ga = rm & 7, r8 = rm >> 3;
            const float* pv = &va.x;
#pragma unroll
            for (int e = 0; e < 4; e++) {
                int cc = c4 + e;
                int kf = cc >> 3, cm = cc & 7;
                int tt = cm & 3, rk = cm >> 2;
                int idx = (kf * 8 + mt) * 128 + (ga * 4 + tt) * 4 + r8 + 2 * rk;
                float v = pv[e];
                unsigned hu = f2tf32(v);
                float hf = __uint_as_float(hu);
                sm[AH + idx] = hf;
                sm[AL + idx] = __uint_as_float(f2tf32(v - hf));
            }

            float4 vb = *reinterpret_cast<const float4*>(&W[(size_t)(n0 + r) * K + k0 + c4]);
            int nt = r >> 3, rn = r & 7;
            const float* pw = &vb.x;
#pragma unroll
            for (int e = 0; e < 4; e++) {
                int cc = c4 + e;
                int kf = cc >> 3, cm = cc & 7;
                int tt = cm & 3, rk = cm >> 2;
                int idx = (kf * 16 + nt) * 64 + (rn * 4 + tt) * 2 + rk;
                float v = pw[e];
                unsigned hu = f2tf32(v);
                float hf = __uint_as_float(hu);
                sm[BH + idx] = hf;
                sm[BL + idx] = __uint_as_float(f2tf32(v - hf));
            }
        }
        __syncthreads();

        // ---- compute: 2 k8 steps, 3-mma split ----
#pragma unroll
        for (int kf = 0; kf < 2; kf++) {
            unsigned ah[2][4], al[2][4];
#pragma unroll
            for (int mt2 = 0; mt2 < 2; mt2++) {
                int base = (kf * 8 + wm * 2 + mt2) * 128 + lane * 4;
                float4 h4 = *reinterpret_cast<const float4*>(&sm[AH + base]);
                float4 l4 = *reinterpret_cast<const float4*>(&sm[AL + base]);
                ah[mt2][0] = __float_as_uint(h4.x); ah[mt2][1] = __float_as_uint(h4.y);
                ah[mt2][2] = __float_as_uint(h4.z); ah[mt2][3] = __float_as_uint(h4.w);
                al[mt2][0] = __float_as_uint(l4.x); al[mt2][1] = __float_as_uint(l4.y);
                al[mt2][2] = __float_as_uint(l4.z); al[mt2][3] = __float_as_uint(l4.w);
            }
#pragma unroll
            for (int nf = 0; nf < 8; nf++) {
                int baseb = (kf * 16 + wn * 8 + nf) * 64 + lane * 2;
                unsigned bh0 = __float_as_uint(sm[BH + baseb]);
                unsigned bh1 = __float_as_uint(sm[BH + baseb + 1]);
                unsigned bl0 = __float_as_uint(sm[BL + baseb]);
                unsigned bl1 = __float_as_uint(sm[BL + baseb + 1]);
#pragma unroll
                for (int mt2 = 0; mt2 < 2; mt2++) {
                    mma8(c[mt2][nf], ah[mt2], bh0, bh1);
                    mma8(c[mt2][nf], ah[mt2], bl0, bl1);
                    mma8(c[mt2][nf], al[mt2], bh0, bh1);
                }
            }
        }
        __syncthreads();
    }

    // ---- epilogue ----
#pragma unroll
    for (int mt2 = 0; mt2 < 2; mt2++) {
#pragma unroll
        for (int nf = 0; nf < 8; nf++) {
            int col = n0 + wn * 64 + nf * 8 + 2 * t;
            float b0v = bias[col], b1v = bias[col + 1];
            int row0 = m0 + wm * 32 + mt2 * 16 + g;
            *reinterpret_cast<float2*>(&C[(size_t)row0 * N + col]) =
                make_float2(c[mt2][nf][0] + b0v, c[mt2][nf][1] + b1v);
            *reinterpret_cast<float2*>(&C[(size_t)(row0 + 8) * N + col]) =
                make_float2(c[mt2][nf][2] + b0v, c[mt2][nf][3] + b1v);
        }
    }
}

// ---------------------------------------------------------------------------
// Flash attention, tf32 mma. Q-block 128 rows, K-tile 64 tokens, d=64.
// 8 warps, each owns 16 q-rows; S and O live in mma C-fragments.
// P round-trips through warp-private smem to convert C-layout -> A-layout.
// smem pads: Ks 68 (stride%32==4: conflict-free for row-by-g access),
//            Vs 72 (stride%32==8: conflict-free for row-by-t access),
//            Ps 68.
// ---------------------------------------------------------------------------
#define KPAD 68
#define VPAD 72
#define PPAD 68
#define FL_SMEM ((64 * KPAD + 64 * VPAD + 128 * PPAD) * 4)   // 70656 B

__global__ __launch_bounds__(256, 2)
void flash_tf32(const float* __restrict__ Q, const float* __restrict__ Kg,
                const float* __restrict__ Vg, float* __restrict__ O)
{
    extern __shared__ float sm[];
    float* Ks = sm;                     // 64 * KPAD
    float* Vs = sm + 64 * KPAD;         // 64 * VPAD
    float* Ps = sm + 64 * KPAD + 64 * VPAD;  // 128 * PPAD

    const int tid  = threadIdx.x;
    const int lane = tid & 31;
    const int warp = tid >> 5;
    const int g = lane >> 2, t = lane & 3;

    const int qb = 15 - blockIdx.x;     // reversed: big blocks first
    const int qstart = qb * 128;
    const int bh = blockIdx.y;
    const int b = bh >> 4;
    const int h = bh & 15;
    const int rowbase = b * T_SEQ;
    const int hoff = h * D_HEAD;

    // Q fragments (pre-scaled for exp2 domain), kept in registers for all tiles
    const float qs = 0.125f * 1.4426950408889634f;   // 1/sqrt(64) * 1/ln(2)
    unsigned qa[8][4];
    {
        int r0 = rowbase + qstart + warp * 16 + g;
#pragma unroll
        for (int kf = 0; kf < 8; kf++) {
            int colx = hoff + kf * 8 + t;
            qa[kf][0] = f2tf32(qs * Q[(size_t)r0 * D_MODEL + colx]);
            qa[kf][1] = f2tf32(qs * Q[(size_t)(r0 + 8) * D_MODEL + colx]);
            qa[kf][2] = f2tf32(qs * Q[(size_t)r0 * D_MODEL + colx + 4]);
            qa[kf][3] = f2tf32(qs * Q[(size_t)(r0 + 8) * D_MODEL + colx + 4]);
        }
    }

    float o[8][4];
#pragma unroll
    for (int nf = 0; nf < 8; nf++)
#pragma unroll
        for (int e = 0; e < 4; e++) o[nf][e] = 0.f;
    float mr0 = -INFINITY, mr1 = -INFINITY, l0 = 0.f, l1 = 0.f;

    const int ktmax = 2 * qb + 1;
    for (int kt = 0; kt <= ktmax; kt++) {
        const int kb = kt * 64;

        // ---- stage K,V tiles (tf32-rounded) ----
#pragma unroll
        for (int hh = 0; hh < 4; hh++) {
            int fid = tid + hh * 256;        // 0..1023
            int rr = fid >> 4;               // 0..63
            int cc = (fid & 15) * 4;         // 0..60
            float4 kv = *reinterpret_cast<const float4*>(
                &Kg[(size_t)(rowbase + kb + rr) * D_MODEL + hoff + cc]);
            float4 ko = make_float4(tf32r(kv.x), tf32r(kv.y), tf32r(kv.z), tf32r(kv.w));
            *reinterpret_cast<float4*>(&Ks[rr * KPAD + cc]) = ko;
            float4 vv = *reinterpret_cast<const float4*>(
                &Vg[(size_t)(rowbase + kb + rr) * D_MODEL + hoff + cc]);
            float4 vo = make_float4(tf32r(vv.x), tf32r(vv.y), tf32r(vv.z), tf32r(vv.w));
            *reinterpret_cast<float4*>(&Vs[rr * VPAD + cc]) = vo;
        }
        __syncthreads();

        // ---- S = Q @ K^T (in exp2 domain) ----
        float s[8][4];
#pragma unroll
        for (int nf = 0; nf < 8; nf++)
#pragma unroll
            for (int e = 0; e < 4; e++) s[nf][e] = 0.f;

#pragma unroll
        for (int kf = 0; kf < 8; kf++) {
#pragma unroll
            for (int nf = 0; nf < 8; nf++) {
                unsigned b0 = __float_as_uint(Ks[(nf * 8 + g) * KPAD + kf * 8 + t]);
                unsigned b1 = __float_as_uint(Ks[(nf * 8 + g) * KPAD + kf * 8 + t + 4]);
                mma8(s[nf], qa[kf], b0, b1);
            }
        }

        // ---- causal mask (only needed on the two diagonal-straddling tiles) ----
        if (kt >= 2 * qb) {
            int rb = qstart + warp * 16 + g;
#pragma unroll
            for (int nf = 0; nf < 8; nf++) {
                int c0 = kb + nf * 8 + 2 * t;
                if (c0     > rb)     s[nf][0] = -INFINITY;
                if (c0 + 1 > rb)     s[nf][1] = -INFINITY;
                if (c0     > rb + 8) s[nf][2] = -INFINITY;
                if (c0 + 1 > rb + 8) s[nf][3] = -INFINITY;
            }
        }

        // ---- online softmax (rows g and g+8; 4 lanes/row share via shfl) ----
        float mx0 = -INFINITY, mx1 = -INFINITY;
#pragma unroll
        for (int nf = 0; nf < 8; nf++) {
            mx0 = fmaxf(mx0, fmaxf(s[nf][0], s[nf][1]));
            mx1 = fmaxf(mx1, fmaxf(s[nf][2], s[nf][3]));
        }
        mx0 = fmaxf(mx0, __shfl_xor_sync(0xffffffffu, mx0, 1));
        mx0 = fmaxf(mx0, __shfl_xor_sync(0xffffffffu, mx0, 2));
        mx1 = fmaxf(mx1, __shfl_xor_sync(0xffffffffu, mx1, 1));
        mx1 = fmaxf(mx1, __shfl_xor_sync(0xffffffffu, mx1, 2));

        float mn0 = fmaxf(mr0, mx0), mn1 = fmaxf(mr1, mx1);
        float corr0 = ex2f(mr0 - mn0), corr1 = ex2f(mr1 - mn1);
        float sum0 = 0.f, sum1 = 0.f;
#pragma unroll
        for (int nf = 0; nf < 8; nf++) {
            s[nf][0] = ex2f(s[nf][0] - mn0); sum0 += s[nf][0];
            s[nf][1] = ex2f(s[nf][1] - mn0); sum0 += s[nf][1];
            s[nf][2] = ex2f(s[nf][2] - mn1); sum1 += s[nf][2];
            s[nf][3] = ex2f(s[nf][3] - mn1); sum1 += s[nf][3];
        }
        sum0 += __shfl_xor_sync(0xffffffffu, sum0, 1);
        sum0 += __shfl_xor_sync(0xffffffffu, sum0, 2);
        sum1 += __shfl_xor_sync(0xffffffffu, sum1, 1);
        sum1 += __shfl_xor_sync(0xffffffffu, sum1, 2);

        l0 = l0 * corr0 + sum0;  mr0 = mn0;
        l1 = l1 * corr1 + sum1;  mr1 = mn1;
#pragma unroll
        for (int nf = 0; nf < 8; nf++) {
            o[nf][0] *= corr0; o[nf][1] *= corr0;
            o[nf][2] *= corr1; o[nf][3] *= corr1;
        }

        // ---- store P (tf32-rounded) to warp-private smem rows ----
        {
            int pr0 = warp * 16 + g;
#pragma unroll
            for (int nf = 0; nf < 8; nf++) {
                int pc = nf * 8 + 2 * t;
                Ps[pr0 * PPAD + pc]       = __uint_as_float(f2tf32(s[nf][0]));
                Ps[pr0 * PPAD + pc + 1]   = __uint_as_float(f2tf32(s[nf][1]));
                Ps[(pr0 + 8) * PPAD + pc]     = __uint_as_float(f2tf32(s[nf][2]));
                Ps[(pr0 + 8) * PPAD + pc + 1] = __uint_as_float(f2tf32(s[nf][3]));
            }
        }
        __syncwarp();   // warp-local P visibility (no cross-warp dependency)

        // ---- O += P @ V ----
#pragma unroll
        for (int kf = 0; kf < 8; kf++) {
            unsigned pa[4];
            int pr = warp * 16 + g;
            pa[0] = __float_as_uint(Ps[pr * PPAD + kf * 8 + t]);
            pa[1] = __float_as_uint(Ps[(pr + 8) * PPAD + kf * 8 + t]);
            pa[2] = __float_as_uint(Ps[pr * PPAD + kf * 8 + t + 4]);
            pa[3] = __float_as_uint(Ps[(pr + 8) * PPAD + kf * 8 + t + 4]);
#pragma unroll
            for (int nf = 0; nf < 8; nf++) {
                unsigned b0 = __float_as_uint(Vs[(kf * 8 + t) * VPAD + nf * 8 + g]);
                unsigned b1 = __float_as_uint(Vs[(kf * 8 + t + 4) * VPAD + nf * 8 + g]);
                mma8(o[nf], pa, b0, b1);
            }
        }
        __syncthreads();   // protect Ks/Vs before next tile's staging
    }

    // ---- finalize ----
    float inv0 = 1.0f / l0, inv1 = 1.0f / l1;
    int ro0 = rowbase + qstart + warp * 16 + g;
#pragma unroll
    for (int nf = 0; nf < 8; nf++) {
        int colx = hoff + nf * 8 + 2 * t;
        *reinterpret_cast<float2*>(&O[(size_t)ro0 * D_MODEL + colx]) =
            make_float2(o[nf][0] * inv0, o[nf][1] * inv0);
        *reinterpret_cast<float2*>(&O[(size_t)(ro0 + 8) * D_MODEL + colx]) =
            make_float2(o[nf][2] * inv1, o[nf][3] * inv1);
    }
}

// ---------------------------------------------------------------------------
// Launch
// ---------------------------------------------------------------------------
extern "C" void kernel_launch(void* const* d_in, const int* in_sizes, int n_in,
                              void* d_out, int out_size)
{
    const float* x  = (const float*)d_in[0];
    const float* Wq = (const float*)d_in[1];
    const float* bq = (const float*)d_in[2];
    const float* Wk = (const float*)d_in[3];
    const float* bk = (const float*)d_in[4];
    const float* Wv = (const float*)d_in[5];
    const float* bv = (const float*)d_in[6];
    const float* Wo = (const float*)d_in[7];
    const float* bo = (const float*)d_in[8];
    float* out = (float*)d_out;

    float *Qb, *Kb, *Vb, *Ob;
    cudaGetSymbolAddress((void**)&Qb, g_Q);
    cudaGetSymbolAddress((void**)&Kb, g_K);
    cudaGetSymbolAddress((void**)&Vb, g_V);
    cudaGetSymbolAddress((void**)&Ob, g_O);

    dim3 gblock(256);
    dim3 ggrid(D_MODEL / 128, M_ROWS / 128);   // (8, 64)

    gemm_tf32x2<<<ggrid, gblock>>>(x, Wq, bq, Qb, M_ROWS, D_MODEL, D_MODEL);
    gemm_tf32x2<<<ggrid, gblock>>>(x, Wk, bk, Kb, M_ROWS, D_MODEL, D_MODEL);
    gemm_tf32x2<<<ggrid, gblock>>>(x, Wv, bv, Vb, M_ROWS, D_MODEL, D_MODEL);

    cudaFuncSetAttribute(flash_tf32, cudaFuncAttributeMaxDynamicSharedMemorySize, FL_SMEM);
    dim3 fgrid(T_SEQ / 128, B_SZ * N_HEADS);   // (16, 64)
    flash_tf32<<<fgrid, 256, FL_SMEM>>>(Qb, Kb, Vb, Ob);

    gemm_tf32x2<<<ggrid, gblock>>>(Ob, Wo, bo, out, M_ROWS, D_MODEL, D_MODEL);
}

// round 4
// speedup vs baseline: 5.1357x; 2.2818x over previous
#include <cuda_runtime.h>
#include <cuda_bf16.h>
#include <math.h>
#include <stdint.h>

#define D_MODEL 1024
#define N_HEADS 16
#define D_HEAD  64
#define B_SZ    4
#define T_SEQ   2048
#define M_ROWS  (B_SZ * T_SEQ)   // 8192

// ---------------- scratch (allocation-free rule: __device__ globals) --------
__device__ float g_Q[M_ROWS * D_MODEL];
__device__ float g_K[M_ROWS * D_MODEL];
__device__ float g_V[M_ROWS * D_MODEL];
__device__ float g_O[M_ROWS * D_MODEL];
__device__ __nv_bfloat16 g_xhi[M_ROWS * D_MODEL];
__device__ __nv_bfloat16 g_xlo[M_ROWS * D_MODEL];
__device__ __nv_bfloat16 g_ohi[M_ROWS * D_MODEL];
__device__ __nv_bfloat16 g_olo[M_ROWS * D_MODEL];
__device__ __nv_bfloat16 g_whi[D_MODEL * D_MODEL];
__device__ __nv_bfloat16 g_wlo[D_MODEL * D_MODEL];

// ---------------- PTX helpers (all sm_80-compatible) ------------------------
__device__ __forceinline__ uint32_t smem_u32(const void* p) {
    uint32_t a;
    asm("{ .reg .u64 t; cvta.to.shared.u64 t, %1; cvt.u32.u64 %0, t; }" : "=r"(a) : "l"(p));
    return a;
}
__device__ __forceinline__ unsigned f2tf32(float x) {
    unsigned u; asm("cvt.rna.tf32.f32 %0, %1;" : "=r"(u) : "f"(x)); return u;
}
__device__ __forceinline__ float tf32r(float x) { return __uint_as_float(f2tf32(x)); }
__device__ __forceinline__ float ex2f(float x) {
    float y; asm("ex2.approx.f32 %0, %1;" : "=f"(y) : "f"(x)); return y;
}
__device__ __forceinline__ void mma8(float c[4], const unsigned a[4], unsigned b0, unsigned b1) {
    asm("mma.sync.aligned.m16n8k8.row.col.f32.tf32.tf32.f32 "
        "{%0,%1,%2,%3}, {%4,%5,%6,%7}, {%8,%9}, {%0,%1,%2,%3};"
        : "+f"(c[0]), "+f"(c[1]), "+f"(c[2]), "+f"(c[3])
        : "r"(a[0]), "r"(a[1]), "r"(a[2]), "r"(a[3]), "r"(b0), "r"(b1));
}
__device__ __forceinline__ void mma16(float c[4], const uint32_t a[4], uint32_t b0, uint32_t b1) {
    asm("mma.sync.aligned.m16n8k16.row.col.f32.bf16.bf16.f32 "
        "{%0,%1,%2,%3}, {%4,%5,%6,%7}, {%8,%9}, {%0,%1,%2,%3};"
        : "+f"(c[0]), "+f"(c[1]), "+f"(c[2]), "+f"(c[3])
        : "r"(a[0]), "r"(a[1]), "r"(a[2]), "r"(a[3]), "r"(b0), "r"(b1));
}
__device__ __forceinline__ void ldsm4(uint32_t addr, uint32_t r[4]) {
    asm volatile("ldmatrix.sync.aligned.m8n8.x4.shared.b16 {%0,%1,%2,%3}, [%4];"
        : "=r"(r[0]), "=r"(r[1]), "=r"(r[2]), "=r"(r[3]) : "r"(addr));
}
__device__ __forceinline__ void cp16(uint32_t saddr, const void* g) {
    asm volatile("cp.async.cg.shared.global [%0], [%1], 16;" :: "r"(saddr), "l"(g));
}
#define CP_COMMIT() asm volatile("cp.async.commit_group;" ::: "memory")
#define CP_WAIT1()  asm volatile("cp.async.wait_group 1;" ::: "memory")
#define CP_WAIT0()  asm volatile("cp.async.wait_group 0;" ::: "memory")

// ---------------------------------------------------------------------------
// split: fp32 -> bf16 hi + bf16 lo
// ---------------------------------------------------------------------------
__global__ void split_bf16(const float* __restrict__ src,
                           __nv_bfloat16* __restrict__ hi,
                           __nv_bfloat16* __restrict__ lo, int n4)
{
    int i = blockIdx.x * blockDim.x + threadIdx.x;
    if (i >= n4) return;
    float4 v = reinterpret_cast<const float4*>(src)[i];
    __nv_bfloat16 h0 = __float2bfloat16(v.x);
    __nv_bfloat16 h1 = __float2bfloat16(v.y);
    __nv_bfloat16 h2 = __float2bfloat16(v.z);
    __nv_bfloat16 h3 = __float2bfloat16(v.w);
    reinterpret_cast<__nv_bfloat162*>(hi)[2 * i]     = __halves2bfloat162(h0, h1);
    reinterpret_cast<__nv_bfloat162*>(hi)[2 * i + 1] = __halves2bfloat162(h2, h3);
    __nv_bfloat16 l0 = __float2bfloat16(v.x - __bfloat162float(h0));
    __nv_bfloat16 l1 = __float2bfloat16(v.y - __bfloat162float(h1));
    __nv_bfloat16 l2 = __float2bfloat16(v.z - __bfloat162float(h2));
    __nv_bfloat16 l3 = __float2bfloat16(v.w - __bfloat162float(h3));
    reinterpret_cast<__nv_bfloat162*>(lo)[2 * i]     = __halves2bfloat162(l0, l1);
    reinterpret_cast<__nv_bfloat162*>(lo)[2 * i + 1] = __halves2bfloat162(l2, l3);
}

// ---------------------------------------------------------------------------
// GEMM: C[8192,1024] = A @ W^T + bias.  bf16x2 split, mma.m16n8k16, fp32 acc.
// CTA tile 128x128, BK=64, 3-stage cp.async pipeline, 256 threads (8 warps).
// Warp tile 32x64.  SW128 swizzle, ldmatrix fragment loads.
// ---------------------------------------------------------------------------
#define NSLAB 16                   // K / 64
#define AHI_OFF 0
#define ALO_OFF 16384
#define BHI_OFF 32768
#define BLO_OFF 49152
#define STAGE_B 65536
#define G_SMEM (3 * STAGE_B)       // 196608

__global__ __launch_bounds__(256, 1)
void gemm_bf16x2(const __nv_bfloat16* __restrict__ Ahi, const __nv_bfloat16* __restrict__ Alo,
                 const __nv_bfloat16* __restrict__ Bhi, const __nv_bfloat16* __restrict__ Blo,
                 const float* __restrict__ bias, float* __restrict__ C)
{
    extern __shared__ char smem[];
    const uint32_t sb = smem_u32(smem);
    const int tid = threadIdx.x, lane = tid & 31, warp = tid >> 5;
    const int g = lane >> 2, t = lane & 3;
    const int wm = warp >> 1, wn = warp & 1;
    const int m0 = blockIdx.y * 128, n0 = blockIdx.x * 128;

    // cooperative stage load: 16 cp.async x 16B per thread
    auto load_slab = [&](int slab, int stage) {
        const uint32_t st = sb + stage * STAGE_B;
        const int kbyte = slab * 128;              // 64 bf16 = 128 bytes
#pragma unroll
        for (int i = 0; i < 4; i++) {
            int idx = tid + i * 256;               // 0..1023
            int r = idx >> 3, c = idx & 7;
            uint32_t off = r * 128 + c * 16;
            uint32_t sw = off ^ ((off >> 3) & 0x70);
            size_t ga = (size_t)(m0 + r) * 2048 + kbyte + c * 16;
            cp16(st + AHI_OFF + sw, (const char*)Ahi + ga);
            cp16(st + ALO_OFF + sw, (const char*)Alo + ga);
            size_t gb = (size_t)(n0 + r) * 2048 + kbyte + c * 16;
            cp16(st + BHI_OFF + sw, (const char*)Bhi + gb);
            cp16(st + BLO_OFF + sw, (const char*)Blo + gb);
        }
    };

    float acc[2][8][4];
#pragma unroll
    for (int i = 0; i < 2; i++)
#pragma unroll
        for (int j = 0; j < 8; j++)
#pragma unroll
            for (int e = 0; e < 4; e++) acc[i][j][e] = 0.f;

    load_slab(0, 0); CP_COMMIT();
    load_slab(1, 1); CP_COMMIT();

    // precomputed lane pieces for ldmatrix addressing
    const int lr  = lane & 7;
    const int aR8 = ((lane >> 3) & 1) * 8;   // A: row +8 group
    const int aCh = (lane >> 4);             // A: k-chunk +1
    const int bR8 = (lane >> 4) * 8;         // B: row +8 group
    const int bCh = (lane >> 3) & 1;         // B: k-chunk +1

    for (int it = 0; it < NSLAB; it++) {
        const int s = it % 3;
        if (it == NSLAB - 1) { CP_WAIT0(); } else { CP_WAIT1(); }
        __syncthreads();

        const uint32_t stA_h = sb + s * STAGE_B + AHI_OFF;
        const uint32_t stA_l = sb + s * STAGE_B + ALO_OFF;
        const uint32_t stB_h = sb + s * STAGE_B + BHI_OFF;
        const uint32_t stB_l = sb + s * STAGE_B + BLO_OFF;

#pragma unroll
        for (int ks = 0; ks < 4; ks++) {
            uint32_t ah[2][4], al[2][4];
#pragma unroll
            for (int mt = 0; mt < 2; mt++) {
                int row = wm * 32 + mt * 16 + aR8 + lr;
                int ch  = ks * 2 + aCh;
                uint32_t off = row * 128 + ch * 16;
                uint32_t sw = off ^ ((off >> 3) & 0x70);
                ldsm4(stA_h + sw, ah[mt]);
                ldsm4(stA_l + sw, al[mt]);
            }
            uint32_t bh[4][4], bl[4][4];
#pragma unroll
            for (int np = 0; np < 4; np++) {
                int row = wn * 64 + np * 16 + bR8 + lr;
                int ch  = ks * 2 + bCh;
                uint32_t off = row * 128 + ch * 16;
                uint32_t sw = off ^ ((off >> 3) & 0x70);
                ldsm4(stB_h + sw, bh[np]);
                ldsm4(stB_l + sw, bl[np]);
            }
#pragma unroll
            for (int mt = 0; mt < 2; mt++) {
#pragma unroll
                for (int nf = 0; nf < 8; nf++) {
                    uint32_t b0h = bh[nf >> 1][(nf & 1) * 2];
                    uint32_t b1h = bh[nf >> 1][(nf & 1) * 2 + 1];
                    uint32_t b0l = bl[nf >> 1][(nf & 1) * 2];
                    uint32_t b1l = bl[nf >> 1][(nf & 1) * 2 + 1];
                    mma16(acc[mt][nf], ah[mt], b0h, b1h);
                    mma16(acc[mt][nf], ah[mt], b0l, b1l);
                    mma16(acc[mt][nf], al[mt], b0h, b1h);
                }
            }
        }
        __syncthreads();
        if (it + 2 < NSLAB) { load_slab(it + 2, (it + 2) % 3); CP_COMMIT(); }
    }

    // epilogue with bias
#pragma unroll
    for (int mt = 0; mt < 2; mt++) {
#pragma unroll
        for (int nf = 0; nf < 8; nf++) {
            int col = n0 + wn * 64 + nf * 8 + 2 * t;
            float b0v = bias[col], b1v = bias[col + 1];
            int row0 = m0 + wm * 32 + mt * 16 + g;
            *reinterpret_cast<float2*>(&C[(size_t)row0 * D_MODEL + col]) =
                make_float2(acc[mt][nf][0] + b0v, acc[mt][nf][1] + b1v);
            *reinterpret_cast<float2*>(&C[(size_t)(row0 + 8) * D_MODEL + col]) =
                make_float2(acc[mt][nf][2] + b0v, acc[mt][nf][3] + b1v);
        }
    }
}

// ---------------------------------------------------------------------------
// Flash attention (round-2, proven): tf32 mma, Q-block 128, K-tile 64
// ---------------------------------------------------------------------------
#define KPAD 68
#define VPAD 72
#define PPAD 68
#define FL_SMEM ((64 * KPAD + 64 * VPAD + 128 * PPAD) * 4)

__global__ __launch_bounds__(256, 2)
void flash_tf32(const float* __restrict__ Q, const float* __restrict__ Kg,
                const float* __restrict__ Vg, float* __restrict__ O)
{
    extern __shared__ float sm[];
    float* Ks = sm;
    float* Vs = sm + 64 * KPAD;
    float* Ps = sm + 64 * KPAD + 64 * VPAD;

    const int tid  = threadIdx.x;
    const int lane = tid & 31;
    const int warp = tid >> 5;
    const int g = lane >> 2, t = lane & 3;

    const int qb = 15 - blockIdx.x;
    const int qstart = qb * 128;
    const int bh = blockIdx.y;
    const int b = bh >> 4;
    const int h = bh & 15;
    const int rowbase = b * T_SEQ;
    const int hoff = h * D_HEAD;

    const float qs = 0.125f * 1.4426950408889634f;
    unsigned qa[8][4];
    {
        int r0 = rowbase + qstart + warp * 16 + g;
#pragma unroll
        for (int kf = 0; kf < 8; kf++) {
            int colx = hoff + kf * 8 + t;
            qa[kf][0] = f2tf32(qs * Q[(size_t)r0 * D_MODEL + colx]);
            qa[kf][1] = f2tf32(qs * Q[(size_t)(r0 + 8) * D_MODEL + colx]);
            qa[kf][2] = f2tf32(qs * Q[(size_t)r0 * D_MODEL + colx + 4]);
            qa[kf][3] = f2tf32(qs * Q[(size_t)(r0 + 8) * D_MODEL + colx + 4]);
        }
    }

    float o[8][4];
#pragma unroll
    for (int nf = 0; nf < 8; nf++)
#pragma unroll
        for (int e = 0; e < 4; e++) o[nf][e] = 0.f;
    float mr0 = -INFINITY, mr1 = -INFINITY, l0 = 0.f, l1 = 0.f;

    const int ktmax = 2 * qb + 1;
    for (int kt = 0; kt <= ktmax; kt++) {
        const int kb = kt * 64;
#pragma unroll
        for (int hh = 0; hh < 4; hh++) {
            int fid = tid + hh * 256;
            int rr = fid >> 4;
            int cc = (fid & 15) * 4;
            float4 kv = *reinterpret_cast<const float4*>(
                &Kg[(size_t)(rowbase + kb + rr) * D_MODEL + hoff + cc]);
            *reinterpret_cast<float4*>(&Ks[rr * KPAD + cc]) =
                make_float4(tf32r(kv.x), tf32r(kv.y), tf32r(kv.z), tf32r(kv.w));
            float4 vv = *reinterpret_cast<const float4*>(
                &Vg[(size_t)(rowbase + kb + rr) * D_MODEL + hoff + cc]);
            *reinterpret_cast<float4*>(&Vs[rr * VPAD + cc]) =
                make_float4(tf32r(vv.x), tf32r(vv.y), tf32r(vv.z), tf32r(vv.w));
        }
        __syncthreads();

        float s[8][4];
#pragma unroll
        for (int nf = 0; nf < 8; nf++)
#pragma unroll
            for (int e = 0; e < 4; e++) s[nf][e] = 0.f;

#pragma unroll
        for (int kf = 0; kf < 8; kf++) {
#pragma unroll
            for (int nf = 0; nf < 8; nf++) {
                unsigned b0 = __float_as_uint(Ks[(nf * 8 + g) * KPAD + kf * 8 + t]);
                unsigned b1 = __float_as_uint(Ks[(nf * 8 + g) * KPAD + kf * 8 + t + 4]);
                mma8(s[nf], qa[kf], b0, b1);
            }
        }

        if (kt >= 2 * qb) {
            int rb = qstart + warp * 16 + g;
#pragma unroll
            for (int nf = 0; nf < 8; nf++) {
                int c0 = kb + nf * 8 + 2 * t;
                if (c0     > rb)     s[nf][0] = -INFINITY;
                if (c0 + 1 > rb)     s[nf][1] = -INFINITY;
                if (c0     > rb + 8) s[nf][2] = -INFINITY;
                if (c0 + 1 > rb + 8) s[nf][3] = -INFINITY;
            }
        }

        float mx0 = -INFINITY, mx1 = -INFINITY;
#pragma unroll
        for (int nf = 0; nf < 8; nf++) {
            mx0 = fmaxf(mx0, fmaxf(s[nf][0], s[nf][1]));
            mx1 = fmaxf(mx1, fmaxf(s[nf][2], s[nf][3]));
        }
        mx0 = fmaxf(mx0, __shfl_xor_sync(0xffffffffu, mx0, 1));
        mx0 = fmaxf(mx0, __shfl_xor_sync(0xffffffffu, mx0, 2));
        mx1 = fmaxf(mx1, __shfl_xor_sync(0xffffffffu, mx1, 1));
        mx1 = fmaxf(mx1, __shfl_xor_sync(0xffffffffu, mx1, 2));

        float mn0 = fmaxf(mr0, mx0), mn1 = fmaxf(mr1, mx1);
        float corr0 = ex2f(mr0 - mn0), corr1 = ex2f(mr1 - mn1);
        float sum0 = 0.f, sum1 = 0.f;
#pragma unroll
        for (int nf = 0; nf < 8; nf++) {
            s[nf][0] = ex2f(s[nf][0] - mn0); sum0 += s[nf][0];
            s[nf][1] = ex2f(s[nf][1] - mn0); sum0 += s[nf][1];
            s[nf][2] = ex2f(s[nf][2] - mn1); sum1 += s[nf][2];
            s[nf][3] = ex2f(s[nf][3] - mn1); sum1 += s[nf][3];
        }
        sum0 += __shfl_xor_sync(0xffffffffu, sum0, 1);
        sum0 += __shfl_xor_sync(0xffffffffu, sum0, 2);
        sum1 += __shfl_xor_sync(0xffffffffu, sum1, 1);
        sum1 += __shfl_xor_sync(0xffffffffu, sum1, 2);

        l0 = l0 * corr0 + sum0;  mr0 = mn0;
        l1 = l1 * corr1 + sum1;  mr1 = mn1;
#pragma unroll
        for (int nf = 0; nf < 8; nf++) {
            o[nf][0] *= corr0; o[nf][1] *= corr0;
            o[nf][2] *= corr1; o[nf][3] *= corr1;
        }

        {
            int pr0 = warp * 16 + g;
#pragma unroll
            for (int nf = 0; nf < 8; nf++) {
                int pc = nf * 8 + 2 * t;
                Ps[pr0 * PPAD + pc]           = __uint_as_float(f2tf32(s[nf][0]));
                Ps[pr0 * PPAD + pc + 1]       = __uint_as_float(f2tf32(s[nf][1]));
                Ps[(pr0 + 8) * PPAD + pc]     = __uint_as_float(f2tf32(s[nf][2]));
                Ps[(pr0 + 8) * PPAD + pc + 1] = __uint_as_float(f2tf32(s[nf][3]));
            }
        }
        __syncwarp();

#pragma unroll
        for (int kf = 0; kf < 8; kf++) {
            unsigned pa[4];
            int pr = warp * 16 + g;
            pa[0] = __float_as_uint(Ps[pr * PPAD + kf * 8 + t]);
            pa[1] = __float_as_uint(Ps[(pr + 8) * PPAD + kf * 8 + t]);
            pa[2] = __float_as_uint(Ps[pr * PPAD + kf * 8 + t + 4]);
            pa[3] = __float_as_uint(Ps[(pr + 8) * PPAD + kf * 8 + t + 4]);
#pragma unroll
            for (int nf = 0; nf < 8; nf++) {
                unsigned b0 = __float_as_uint(Vs[(kf * 8 + t) * VPAD + nf * 8 + g]);
                unsigned b1 = __float_as_uint(Vs[(kf * 8 + t + 4) * VPAD + nf * 8 + g]);
                mma8(o[nf], pa, b0, b1);
            }
        }
        __syncthreads();
    }

    float inv0 = 1.0f / l0, inv1 = 1.0f / l1;
    int ro0 = rowbase + qstart + warp * 16 + g;
#pragma unroll
    for (int nf = 0; nf < 8; nf++) {
        int colx = hoff + nf * 8 + 2 * t;
        *reinterpret_cast<float2*>(&O[(size_t)ro0 * D_MODEL + colx]) =
            make_float2(o[nf][0] * inv0, o[nf][1] * inv0);
        *reinterpret_cast<float2*>(&O[(size_t)(ro0 + 8) * D_MODEL + colx]) =
            make_float2(o[nf][2] * inv1, o[nf][3] * inv1);
    }
}

// ---------------------------------------------------------------------------
// Launch
// ---------------------------------------------------------------------------
extern "C" void kernel_launch(void* const* d_in, const int* in_sizes, int n_in,
                              void* d_out, int out_size)
{
    const float* x  = (const float*)d_in[0];
    const float* Wq = (const float*)d_in[1];
    const float* bq = (const float*)d_in[2];
    const float* Wk = (const float*)d_in[3];
    const float* bk = (const float*)d_in[4];
    const float* Wv = (const float*)d_in[5];
    const float* bv = (const float*)d_in[6];
    const float* Wo = (const float*)d_in[7];
    const float* bo = (const float*)d_in[8];
    float* out = (float*)d_out;

    float *Qb, *Kb, *Vb, *Ob;
    __nv_bfloat16 *xhi, *xlo, *ohi, *olo, *whi, *wlo;
    cudaGetSymbolAddress((void**)&Qb, g_Q);
    cudaGetSymbolAddress((void**)&Kb, g_K);
    cudaGetSymbolAddress((void**)&Vb, g_V);
    cudaGetSymbolAddress((void**)&Ob, g_O);
    cudaGetSymbolAddress((void**)&xhi, g_xhi);
    cudaGetSymbolAddress((void**)&xlo, g_xlo);
    cudaGetSymbolAddress((void**)&ohi, g_ohi);
    cudaGetSymbolAddress((void**)&olo, g_olo);
    cudaGetSymbolAddress((void**)&whi, g_whi);
    cudaGetSymbolAddress((void**)&wlo, g_wlo);

    cudaFuncSetAttribute(gemm_bf16x2, cudaFuncAttributeMaxDynamicSharedMemorySize, G_SMEM);
    cudaFuncSetAttribute(flash_tf32, cudaFuncAttributeMaxDynamicSharedMemorySize, FL_SMEM);

    const int n4x = M_ROWS * D_MODEL / 4;
    const int n4w = D_MODEL * D_MODEL / 4;
    dim3 ggrid(D_MODEL / 128, M_ROWS / 128);     // (8, 64)

    split_bf16<<<n4x / 256, 256>>>(x, xhi, xlo, n4x);

    split_bf16<<<n4w / 256, 256>>>(Wq, whi, wlo, n4w);
    gemm_bf16x2<<<ggrid, 256, G_SMEM>>>(xhi, xlo, whi, wlo, bq, Qb);
    split_bf16<<<n4w / 256, 256>>>(Wk, whi, wlo, n4w);
    gemm_bf16x2<<<ggrid, 256, G_SMEM>>>(xhi, xlo, whi, wlo, bk, Kb);
    split_bf16<<<n4w / 256, 256>>>(Wv, whi, wlo, n4w);
    gemm_bf16x2<<<ggrid, 256, G_SMEM>>>(xhi, xlo, whi, wlo, bv, Vb);

    dim3 fgrid(T_SEQ / 128, B_SZ * N_HEADS);     // (16, 64)
    flash_tf32<<<fgrid, 256, FL_SMEM>>>(Qb, Kb, Vb, Ob);

    split_bf16<<<n4x / 256, 256>>>(Ob, ohi, olo, n4x);
    split_bf16<<<n4w / 256, 256>>>(Wo, whi, wlo, n4w);
    gemm_bf16x2<<<ggrid, 256, G_SMEM>>>(ohi, olo, whi, wlo, bo, out);
}

// round 5
// speedup vs baseline: 5.5419x; 1.0791x over previous
#include <cuda_runtime.h>
#include <cuda_bf16.h>
#include <math.h>
#include <stdint.h>

#define D_MODEL 1024
#define N_HEADS 16
#define D_HEAD  64
#define B_SZ    4
#define T_SEQ   2048
#define M_ROWS  (B_SZ * T_SEQ)   // 8192

// ---------------- scratch (allocation-free rule: __device__ globals) --------
__device__ float g_Q[M_ROWS * D_MODEL];
__device__ float g_K[M_ROWS * D_MODEL];
__device__ float g_V[M_ROWS * D_MODEL];
__device__ float g_O[M_ROWS * D_MODEL];
__device__ __nv_bfloat16 g_xhi[M_ROWS * D_MODEL];
__device__ __nv_bfloat16 g_xlo[M_ROWS * D_MODEL];
__device__ __nv_bfloat16 g_ohi[M_ROWS * D_MODEL];
__device__ __nv_bfloat16 g_olo[M_ROWS * D_MODEL];
__device__ __nv_bfloat16 g_whi[3 * D_MODEL * D_MODEL];
__device__ __nv_bfloat16 g_wlo[3 * D_MODEL * D_MODEL];

// ---------------- PTX helpers (all sm_80-compatible) ------------------------
__device__ __forceinline__ uint32_t smem_u32(const void* p) {
    uint32_t a;
    asm("{ .reg .u64 t; cvta.to.shared.u64 t, %1; cvt.u32.u64 %0, t; }" : "=r"(a) : "l"(p));
    return a;
}
__device__ __forceinline__ unsigned f2tf32(float x) {
    unsigned u; asm("cvt.rna.tf32.f32 %0, %1;" : "=r"(u) : "f"(x)); return u;
}
__device__ __forceinline__ float tf32r(float x) { return __uint_as_float(f2tf32(x)); }
__device__ __forceinline__ float ex2f(float x) {
    float y; asm("ex2.approx.f32 %0, %1;" : "=f"(y) : "f"(x)); return y;
}
__device__ __forceinline__ void mma8(float c[4], const unsigned a[4], unsigned b0, unsigned b1) {
    asm("mma.sync.aligned.m16n8k8.row.col.f32.tf32.tf32.f32 "
        "{%0,%1,%2,%3}, {%4,%5,%6,%7}, {%8,%9}, {%0,%1,%2,%3};"
        : "+f"(c[0]), "+f"(c[1]), "+f"(c[2]), "+f"(c[3])
        : "r"(a[0]), "r"(a[1]), "r"(a[2]), "r"(a[3]), "r"(b0), "r"(b1));
}
__device__ __forceinline__ void mma16(float c[4], const uint32_t a[4], uint32_t b0, uint32_t b1) {
    asm("mma.sync.aligned.m16n8k16.row.col.f32.bf16.bf16.f32 "
        "{%0,%1,%2,%3}, {%4,%5,%6,%7}, {%8,%9}, {%0,%1,%2,%3};"
        : "+f"(c[0]), "+f"(c[1]), "+f"(c[2]), "+f"(c[3])
        : "r"(a[0]), "r"(a[1]), "r"(a[2]), "r"(a[3]), "r"(b0), "r"(b1));
}
__device__ __forceinline__ void ldsm4(uint32_t addr, uint32_t r[4]) {
    asm volatile("ldmatrix.sync.aligned.m8n8.x4.shared.b16 {%0,%1,%2,%3}, [%4];"
        : "=r"(r[0]), "=r"(r[1]), "=r"(r[2]), "=r"(r[3]) : "r"(addr));
}
__device__ __forceinline__ void cp16(uint32_t saddr, const void* g) {
    asm volatile("cp.async.cg.shared.global [%0], [%1], 16;" :: "r"(saddr), "l"(g));
}
#define CP_COMMIT() asm volatile("cp.async.commit_group;" ::: "memory")
#define CP_WAIT1()  asm volatile("cp.async.wait_group 1;" ::: "memory")
#define CP_WAIT0()  asm volatile("cp.async.wait_group 0;" ::: "memory")

// ---------------------------------------------------------------------------
// split: fp32 -> bf16 hi + bf16 lo
// ---------------------------------------------------------------------------
__global__ void split_bf16(const float* __restrict__ src,
                           __nv_bfloat16* __restrict__ hi,
                           __nv_bfloat16* __restrict__ lo, int n4)
{
    int i = blockIdx.x * blockDim.x + threadIdx.x;
    if (i >= n4) return;
    float4 v = reinterpret_cast<const float4*>(src)[i];
    __nv_bfloat16 h0 = __float2bfloat16(v.x);
    __nv_bfloat16 h1 = __float2bfloat16(v.y);
    __nv_bfloat16 h2 = __float2bfloat16(v.z);
    __nv_bfloat16 h3 = __float2bfloat16(v.w);
    reinterpret_cast<__nv_bfloat162*>(hi)[2 * i]     = __halves2bfloat162(h0, h1);
    reinterpret_cast<__nv_bfloat162*>(hi)[2 * i + 1] = __halves2bfloat162(h2, h3);
    __nv_bfloat16 l0 = __float2bfloat16(v.x - __bfloat162float(h0));
    __nv_bfloat16 l1 = __float2bfloat16(v.y - __bfloat162float(h1));
    __nv_bfloat16 l2 = __float2bfloat16(v.z - __bfloat162float(h2));
    __nv_bfloat16 l3 = __float2bfloat16(v.w - __bfloat162float(h3));
    reinterpret_cast<__nv_bfloat162*>(lo)[2 * i]     = __halves2bfloat162(l0, l1);
    reinterpret_cast<__nv_bfloat162*>(lo)[2 * i + 1] = __halves2bfloat162(l2, l3);
}

// ---------------------------------------------------------------------------
// GEMM: C[8192,1024] = A @ W^T + bias.  bf16x2 split, mma.m16n8k16, fp32 acc.
// CTA tile 128x128, BK=64, 3-stage cp.async pipeline, 256 threads (8 warps).
// blockIdx.z selects among up to 3 weight/bias/output sets (fused QKV).
// ---------------------------------------------------------------------------
#define NSLAB 16                   // K / 64
#define AHI_OFF 0
#define ALO_OFF 16384
#define BHI_OFF 32768
#define BLO_OFF 49152
#define STAGE_B 65536
#define G_SMEM (3 * STAGE_B)       // 196608

__global__ __launch_bounds__(256, 1)
void gemm_bf16x2(const __nv_bfloat16* __restrict__ Ahi, const __nv_bfloat16* __restrict__ Alo,
                 const __nv_bfloat16* __restrict__ WhiB, const __nv_bfloat16* __restrict__ WloB,
                 const float* __restrict__ bias0, const float* __restrict__ bias1,
                 const float* __restrict__ bias2,
                 float* __restrict__ C0, float* __restrict__ C1, float* __restrict__ C2)
{
    extern __shared__ char smem[];
    const uint32_t sb = smem_u32(smem);
    const int tid = threadIdx.x, lane = tid & 31, warp = tid >> 5;
    const int g = lane >> 2, t = lane & 3;
    const int wm = warp >> 1, wn = warp & 1;
    const int m0 = blockIdx.y * 128, n0 = blockIdx.x * 128;
    const int z = blockIdx.z;

    const __nv_bfloat16* Bhi = WhiB + (size_t)z * D_MODEL * D_MODEL;
    const __nv_bfloat16* Blo = WloB + (size_t)z * D_MODEL * D_MODEL;
    const float* bias = (z == 0) ? bias0 : (z == 1) ? bias1 : bias2;
    float* C = (z == 0) ? C0 : (z == 1) ? C1 : C2;

    auto load_slab = [&](int slab, int stage) {
        const uint32_t st = sb + stage * STAGE_B;
        const int kbyte = slab * 128;              // 64 bf16 = 128 bytes
#pragma unroll
        for (int i = 0; i < 4; i++) {
            int idx = tid + i * 256;               // 0..1023
            int r = idx >> 3, c = idx & 7;
            uint32_t off = r * 128 + c * 16;
            uint32_t sw = off ^ ((off >> 3) & 0x70);
            size_t ga = (size_t)(m0 + r) * 2048 + kbyte + c * 16;
            cp16(st + AHI_OFF + sw, (const char*)Ahi + ga);
            cp16(st + ALO_OFF + sw, (const char*)Alo + ga);
            size_t gb = (size_t)(n0 + r) * 2048 + kbyte + c * 16;
            cp16(st + BHI_OFF + sw, (const char*)Bhi + gb);
            cp16(st + BLO_OFF + sw, (const char*)Blo + gb);
        }
    };

    float acc[2][8][4];
#pragma unroll
    for (int i = 0; i < 2; i++)
#pragma unroll
        for (int j = 0; j < 8; j++)
#pragma unroll
            for (int e = 0; e < 4; e++) acc[i][j][e] = 0.f;

    load_slab(0, 0); CP_COMMIT();
    load_slab(1, 1); CP_COMMIT();

    const int lr  = lane & 7;
    const int aR8 = ((lane >> 3) & 1) * 8;
    const int aCh = (lane >> 4);
    const int bR8 = (lane >> 4) * 8;
    const int bCh = (lane >> 3) & 1;

    for (int it = 0; it < NSLAB; it++) {
        const int s = it % 3;
        if (it == NSLAB - 1) { CP_WAIT0(); } else { CP_WAIT1(); }
        __syncthreads();

        const uint32_t stA_h = sb + s * STAGE_B + AHI_OFF;
        const uint32_t stA_l = sb + s * STAGE_B + ALO_OFF;
        const uint32_t stB_h = sb + s * STAGE_B + BHI_OFF;
        const uint32_t stB_l = sb + s * STAGE_B + BLO_OFF;

#pragma unroll
        for (int ks = 0; ks < 4; ks++) {
            uint32_t ah[2][4], al[2][4];
#pragma unroll
            for (int mt = 0; mt < 2; mt++) {
                int row = wm * 32 + mt * 16 + aR8 + lr;
                int ch  = ks * 2 + aCh;
                uint32_t off = row * 128 + ch * 16;
                uint32_t sw = off ^ ((off >> 3) & 0x70);
                ldsm4(stA_h + sw, ah[mt]);
                ldsm4(stA_l + sw, al[mt]);
            }
            uint32_t bh[4][4], bl[4][4];
#pragma unroll
            for (int np = 0; np < 4; np++) {
                int row = wn * 64 + np * 16 + bR8 + lr;
                int ch  = ks * 2 + bCh;
                uint32_t off = row * 128 + ch * 16;
                uint32_t sw = off ^ ((off >> 3) & 0x70);
                ldsm4(stB_h + sw, bh[np]);
                ldsm4(stB_l + sw, bl[np]);
            }
#pragma unroll
            for (int mt = 0; mt < 2; mt++) {
#pragma unroll
                for (int nf = 0; nf < 8; nf++) {
                    uint32_t b0h = bh[nf >> 1][(nf & 1) * 2];
                    uint32_t b1h = bh[nf >> 1][(nf & 1) * 2 + 1];
                    uint32_t b0l = bl[nf >> 1][(nf & 1) * 2];
                    uint32_t b1l = bl[nf >> 1][(nf & 1) * 2 + 1];
                    mma16(acc[mt][nf], ah[mt], b0h, b1h);
                    mma16(acc[mt][nf], ah[mt], b0l, b1l);
                    mma16(acc[mt][nf], al[mt], b0h, b1h);
                }
            }
        }
        __syncthreads();
        if (it + 2 < NSLAB) { load_slab(it + 2, (it + 2) % 3); CP_COMMIT(); }
    }

#pragma unroll
    for (int mt = 0; mt < 2; mt++) {
#pragma unroll
        for (int nf = 0; nf < 8; nf++) {
            int col = n0 + wn * 64 + nf * 8 + 2 * t;
            float b0v = bias[col], b1v = bias[col + 1];
            int row0 = m0 + wm * 32 + mt * 16 + g;
            *reinterpret_cast<float2*>(&C[(size_t)row0 * D_MODEL + col]) =
                make_float2(acc[mt][nf][0] + b0v, acc[mt][nf][1] + b1v);
            *reinterpret_cast<float2*>(&C[(size_t)(row0 + 8) * D_MODEL + col]) =
                make_float2(acc[mt][nf][2] + b0v, acc[mt][nf][3] + b1v);
        }
    }
}

// ---------------------------------------------------------------------------
// Flash attention v2: tf32 mma, Q-block 128 rows, K-tile 64, 4 warps.
// Warp owns 32 q-rows (2 m-tiles) -> every K/V B-fragment feeds 2 mma8s,
// halving smem traffic per mma vs v1 (the measured bottleneck).
// ---------------------------------------------------------------------------
#define KPAD 68
#define VPAD 72
#define PPAD 68
#define FL_SMEM ((64 * KPAD + 64 * VPAD + 128 * PPAD) * 4)

__global__ __launch_bounds__(128, 2)
void flash_tf32(const float* __restrict__ Q, const float* __restrict__ Kg,
                const float* __restrict__ Vg, float* __restrict__ O)
{
    extern __shared__ float sm[];
    float* Ks = sm;
    float* Vs = sm + 64 * KPAD;
    float* Ps = sm + 64 * KPAD + 64 * VPAD;

    const int tid  = threadIdx.x;
    const int lane = tid & 31;
    const int warp = tid >> 5;          // 0..3
    const int g = lane >> 2, t = lane & 3;

    const int qb = 15 - blockIdx.x;
    const int qstart = qb * 128;
    const int bh = blockIdx.y;
    const int b = bh >> 4;
    const int h = bh & 15;
    const int rowbase = b * T_SEQ;
    const int hoff = h * D_HEAD;

    const float qs = 0.125f * 1.4426950408889634f;
    unsigned qa[2][8][4];
#pragma unroll
    for (int mt = 0; mt < 2; mt++) {
        int r0 = rowbase + qstart + warp * 32 + mt * 16 + g;
#pragma unroll
        for (int kf = 0; kf < 8; kf++) {
            int colx = hoff + kf * 8 + t;
            qa[mt][kf][0] = f2tf32(qs * Q[(size_t)r0 * D_MODEL + colx]);
            qa[mt][kf][1] = f2tf32(qs * Q[(size_t)(r0 + 8) * D_MODEL + colx]);
            qa[mt][kf][2] = f2tf32(qs * Q[(size_t)r0 * D_MODEL + colx + 4]);
            qa[mt][kf][3] = f2tf32(qs * Q[(size_t)(r0 + 8) * D_MODEL + colx + 4]);
        }
    }

    float o[2][8][4];
#pragma unroll
    for (int mt = 0; mt < 2; mt++)
#pragma unroll
        for (int nf = 0; nf < 8; nf++)
#pragma unroll
            for (int e = 0; e < 4; e++) o[mt][nf][e] = 0.f;
    float mr[2][2], lsum[2][2];
#pragma unroll
    for (int mt = 0; mt < 2; mt++) {
        mr[mt][0] = -INFINITY; mr[mt][1] = -INFINITY;
        lsum[mt][0] = 0.f; lsum[mt][1] = 0.f;
    }

    const int ktmax = 2 * qb + 1;
    for (int kt = 0; kt <= ktmax; kt++) {
        const int kb = kt * 64;

        // ---- stage K,V (tf32-rounded); 128 threads x 8 float4 each matrix ----
#pragma unroll
        for (int hh = 0; hh < 8; hh++) {
            int fid = tid + hh * 128;          // 0..1023
            int rr = fid >> 4;
            int cc = (fid & 15) * 4;
            float4 kv = *reinterpret_cast<const float4*>(
                &Kg[(size_t)(rowbase + kb + rr) * D_MODEL + hoff + cc]);
            *reinterpret_cast<float4*>(&Ks[rr * KPAD + cc]) =
                make_float4(tf32r(kv.x), tf32r(kv.y), tf32r(kv.z), tf32r(kv.w));
            float4 vv = *reinterpret_cast<const float4*>(
                &Vg[(size_t)(rowbase + kb + rr) * D_MODEL + hoff + cc]);
            *reinterpret_cast<float4*>(&Vs[rr * VPAD + cc]) =
                make_float4(tf32r(vv.x), tf32r(vv.y), tf32r(vv.z), tf32r(vv.w));
        }
        __syncthreads();

        // ---- S = Q @ K^T : B fragment loaded once, used by both m-tiles ----
        float s[2][8][4];
#pragma unroll
        for (int mt = 0; mt < 2; mt++)
#pragma unroll
            for (int nf = 0; nf < 8; nf++)
#pragma unroll
                for (int e = 0; e < 4; e++) s[mt][nf][e] = 0.f;

#pragma unroll
        for (int kf = 0; kf < 8; kf++) {
#pragma unroll
            for (int nf = 0; nf < 8; nf++) {
                unsigned b0 = __float_as_uint(Ks[(nf * 8 + g) * KPAD + kf * 8 + t]);
                unsigned b1 = __float_as_uint(Ks[(nf * 8 + g) * KPAD + kf * 8 + t + 4]);
                mma8(s[0][nf], qa[0][kf], b0, b1);
                mma8(s[1][nf], qa[1][kf], b0, b1);
            }
        }

        // ---- causal mask on diagonal-straddling tiles ----
        if (kt >= 2 * qb) {
#pragma unroll
            for (int mt = 0; mt < 2; mt++) {
                int rb = qstart + warp * 32 + mt * 16 + g;
#pragma unroll
                for (int nf = 0; nf < 8; nf++) {
                    int c0 = kb + nf * 8 + 2 * t;
                    if (c0     > rb)     s[mt][nf][0] = -INFINITY;
                    if (c0 + 1 > rb)     s[mt][nf][1] = -INFINITY;
                    if (c0     > rb + 8) s[mt][nf][2] = -INFINITY;
                    if (c0 + 1 > rb + 8) s[mt][nf][3] = -INFINITY;
                }
            }
        }

        // ---- online softmax per m-tile ----
#pragma unroll
        for (int mt = 0; mt < 2; mt++) {
            float mx0 = -INFINITY, mx1 = -INFINITY;
#pragma unroll
            for (int nf = 0; nf < 8; nf++) {
                mx0 = fmaxf(mx0, fmaxf(s[mt][nf][0], s[mt][nf][1]));
                mx1 = fmaxf(mx1, fmaxf(s[mt][nf][2], s[mt][nf][3]));
            }
            mx0 = fmaxf(mx0, __shfl_xor_sync(0xffffffffu, mx0, 1));
            mx0 = fmaxf(mx0, __shfl_xor_sync(0xffffffffu, mx0, 2));
            mx1 = fmaxf(mx1, __shfl_xor_sync(0xffffffffu, mx1, 1));
            mx1 = fmaxf(mx1, __shfl_xor_sync(0xffffffffu, mx1, 2));

            float mn0 = fmaxf(mr[mt][0], mx0), mn1 = fmaxf(mr[mt][1], mx1);
            float corr0 = ex2f(mr[mt][0] - mn0), corr1 = ex2f(mr[mt][1] - mn1);
            float sum0 = 0.f, sum1 = 0.f;
#pragma unroll
            for (int nf = 0; nf < 8; nf++) {
                s[mt][nf][0] = ex2f(s[mt][nf][0] - mn0); sum0 += s[mt][nf][0];
                s[mt][nf][1] = ex2f(s[mt][nf][1] - mn0); sum0 += s[mt][nf][1];
                s[mt][nf][2] = ex2f(s[mt][nf][2] - mn1); sum1 += s[mt][nf][2];
                s[mt][nf][3] = ex2f(s[mt][nf][3] - mn1); sum1 += s[mt][nf][3];
            }
            sum0 += __shfl_xor_sync(0xffffffffu, sum0, 1);
            sum0 += __shfl_xor_sync(0xffffffffu, sum0, 2);
            sum1 += __shfl_xor_sync(0xffffffffu, sum1, 1);
            sum1 += __shfl_xor_sync(0xffffffffu, sum1, 2);

            lsum[mt][0] = lsum[mt][0] * corr0 + sum0;  mr[mt][0] = mn0;
            lsum[mt][1] = lsum[mt][1] * corr1 + sum1;  mr[mt][1] = mn1;
#pragma unroll
            for (int nf = 0; nf < 8; nf++) {
                o[mt][nf][0] *= corr0; o[mt][nf][1] *= corr0;
                o[mt][nf][2] *= corr1; o[mt][nf][3] *= corr1;
            }

            // write P (tf32-rounded) to warp-private smem rows
            int pr0 = warp * 32 + mt * 16 + g;
#pragma unroll
            for (int nf = 0; nf < 8; nf++) {
                int pc = nf * 8 + 2 * t;
                Ps[pr0 * PPAD + pc]           = __uint_as_float(f2tf32(s[mt][nf][0]));
                Ps[pr0 * PPAD + pc + 1]       = __uint_as_float(f2tf32(s[mt][nf][1]));
                Ps[(pr0 + 8) * PPAD + pc]     = __uint_as_float(f2tf32(s[mt][nf][2]));
                Ps[(pr0 + 8) * PPAD + pc + 1] = __uint_as_float(f2tf32(s[mt][nf][3]));
            }
        }
        __syncwarp();

        // ---- O += P @ V : V fragment loaded once, used by both m-tiles ----
#pragma unroll
        for (int kf = 0; kf < 8; kf++) {
            unsigned pa[2][4];
#pragma unroll
            for (int mt = 0; mt < 2; mt++) {
                int pr = warp * 32 + mt * 16 + g;
                pa[mt][0] = __float_as_uint(Ps[pr * PPAD + kf * 8 + t]);
                pa[mt][1] = __float_as_uint(Ps[(pr + 8) * PPAD + kf * 8 + t]);
                pa[mt][2] = __float_as_uint(Ps[pr * PPAD + kf * 8 + t + 4]);
                pa[mt][3] = __float_as_uint(Ps[(pr + 8) * PPAD + kf * 8 + t + 4]);
            }
#pragma unroll
            for (int nf = 0; nf < 8; nf++) {
                unsigned b0 = __float_as_uint(Vs[(kf * 8 + t) * VPAD + nf * 8 + g]);
                unsigned b1 = __float_as_uint(Vs[(kf * 8 + t + 4) * VPAD + nf * 8 + g]);
                mma8(o[0][nf], pa[0], b0, b1);
                mma8(o[1][nf], pa[1], b0, b1);
            }
        }
        __syncthreads();
    }

    // ---- finalize ----
#pragma unroll
    for (int mt = 0; mt < 2; mt++) {
        float inv0 = 1.0f / lsum[mt][0], inv1 = 1.0f / lsum[mt][1];
        int ro0 = rowbase + qstart + warp * 32 + mt * 16 + g;
#pragma unroll
        for (int nf = 0; nf < 8; nf++) {
            int colx = hoff + nf * 8 + 2 * t;
            *reinterpret_cast<float2*>(&O[(size_t)ro0 * D_MODEL + colx]) =
                make_float2(o[mt][nf][0] * inv0, o[mt][nf][1] * inv0);
            *reinterpret_cast<float2*>(&O[(size_t)(ro0 + 8) * D_MODEL + colx]) =
                make_float2(o[mt][nf][2] * inv1, o[mt][nf][3] * inv1);
        }
    }
}

// ---------------------------------------------------------------------------
// Launch
// ---------------------------------------------------------------------------
extern "C" void kernel_launch(void* const* d_in, const int* in_sizes, int n_in,
                              void* d_out, int out_size)
{
    const float* x  = (const float*)d_in[0];
    const float* Wq = (const float*)d_in[1];
    const float* bq = (const float*)d_in[2];
    const float* Wk = (const float*)d_in[3];
    const float* bk = (const float*)d_in[4];
    const float* Wv = (const float*)d_in[5];
    const float* bv = (const float*)d_in[6];
    const float* Wo = (const float*)d_in[7];
    const float* bo = (const float*)d_in[8];
    float* out = (float*)d_out;

    float *Qb, *Kb, *Vb, *Ob;
    __nv_bfloat16 *xhi, *xlo, *ohi, *olo, *whi, *wlo;
    cudaGetSymbolAddress((void**)&Qb, g_Q);
    cudaGetSymbolAddress((void**)&Kb, g_K);
    cudaGetSymbolAddress((void**)&Vb, g_V);
    cudaGetSymbolAddress((void**)&Ob, g_O);
    cudaGetSymbolAddress((void**)&xhi, g_xhi);
    cudaGetSymbolAddress((void**)&xlo, g_xlo);
    cudaGetSymbolAddress((void**)&ohi, g_ohi);
    cudaGetSymbolAddress((void**)&olo, g_olo);
    cudaGetSymbolAddress((void**)&whi, g_whi);
    cudaGetSymbolAddress((void**)&wlo, g_wlo);

    cudaFuncSetAttribute(gemm_bf16x2, cudaFuncAttributeMaxDynamicSharedMemorySize, G_SMEM);
    cudaFuncSetAttribute(flash_tf32, cudaFuncAttributeMaxDynamicSharedMemorySize, FL_SMEM);

    const int n4x = M_ROWS * D_MODEL / 4;
    const int n4w = D_MODEL * D_MODEL / 4;
    const size_t wstep = (size_t)D_MODEL * D_MODEL;

    split_bf16<<<n4x / 256, 256>>>(x, xhi, xlo, n4x);
    split_bf16<<<n4w / 256, 256>>>(Wq, whi,             wlo,             n4w);
    split_bf16<<<n4w / 256, 256>>>(Wk, whi + wstep,     wlo + wstep,     n4w);
    split_bf16<<<n4w / 256, 256>>>(Wv, whi + 2 * wstep, wlo + 2 * wstep, n4w);

    dim3 qkvgrid(D_MODEL / 128, M_ROWS / 128, 3);   // (8, 64, 3)
    gemm_bf16x2<<<qkvgrid, 256, G_SMEM>>>(xhi, xlo, whi, wlo, bq, bk, bv, Qb, Kb, Vb);

    dim3 fgrid(T_SEQ / 128, B_SZ * N_HEADS);        // (16, 64)
    flash_tf32<<<fgrid, 128, FL_SMEM>>>(Qb, Kb, Vb, Ob);

    split_bf16<<<n4x / 256, 256>>>(Ob, ohi, olo, n4x);
    split_bf16<<<n4w / 256, 256>>>(Wo, whi, wlo, n4w);
    dim3 ogrid(D_MODEL / 128, M_ROWS / 128, 1);     // (8, 64, 1)
    gemm_bf16x2<<<ogrid, 256, G_SMEM>>>(ohi, olo, whi, wlo, bo, bo, bo, out, out, out);
}

// round 6
// speedup vs baseline: 5.9622x; 1.0758x over previous
#include <cuda_runtime.h>
#include <cuda_bf16.h>
#include <math.h>
#include <stdint.h>

#define D_MODEL 1024
#define N_HEADS 16
#define D_HEAD  64
#define B_SZ    4
#define T_SEQ   2048
#define M_ROWS  (B_SZ * T_SEQ)   // 8192

// ---------------- scratch (allocation-free rule: __device__ globals) --------
__device__ float g_Q[M_ROWS * D_MODEL];
__device__ float g_K[M_ROWS * D_MODEL];
__device__ float g_V[M_ROWS * D_MODEL];
__device__ __nv_bfloat16 g_xhi[M_ROWS * D_MODEL];
__device__ __nv_bfloat16 g_xlo[M_ROWS * D_MODEL];
__device__ __nv_bfloat16 g_ohi[M_ROWS * D_MODEL];
__device__ __nv_bfloat16 g_olo[M_ROWS * D_MODEL];
__device__ __nv_bfloat16 g_whi[4 * D_MODEL * D_MODEL];
__device__ __nv_bfloat16 g_wlo[4 * D_MODEL * D_MODEL];

// ---------------- PTX helpers (all sm_80-compatible) ------------------------
__device__ __forceinline__ uint32_t smem_u32(const void* p) {
    uint32_t a;
    asm("{ .reg .u64 t; cvta.to.shared.u64 t, %1; cvt.u32.u64 %0, t; }" : "=r"(a) : "l"(p));
    return a;
}
__device__ __forceinline__ unsigned f2tf32(float x) {
    unsigned u; asm("cvt.rna.tf32.f32 %0, %1;" : "=r"(u) : "f"(x)); return u;
}
__device__ __forceinline__ float tf32r(float x) { return __uint_as_float(f2tf32(x)); }
__device__ __forceinline__ float ex2f(float x) {
    float y; asm("ex2.approx.f32 %0, %1;" : "=f"(y) : "f"(x)); return y;
}
__device__ __forceinline__ void mma8(float c[4], const unsigned a[4], unsigned b0, unsigned b1) {
    asm("mma.sync.aligned.m16n8k8.row.col.f32.tf32.tf32.f32 "
        "{%0,%1,%2,%3}, {%4,%5,%6,%7}, {%8,%9}, {%0,%1,%2,%3};"
        : "+f"(c[0]), "+f"(c[1]), "+f"(c[2]), "+f"(c[3])
        : "r"(a[0]), "r"(a[1]), "r"(a[2]), "r"(a[3]), "r"(b0), "r"(b1));
}
__device__ __forceinline__ void mma16(float c[4], const uint32_t a[4], uint32_t b0, uint32_t b1) {
    asm("mma.sync.aligned.m16n8k16.row.col.f32.bf16.bf16.f32 "
        "{%0,%1,%2,%3}, {%4,%5,%6,%7}, {%8,%9}, {%0,%1,%2,%3};"
        : "+f"(c[0]), "+f"(c[1]), "+f"(c[2]), "+f"(c[3])
        : "r"(a[0]), "r"(a[1]), "r"(a[2]), "r"(a[3]), "r"(b0), "r"(b1));
}
__device__ __forceinline__ void ldsm4(uint32_t addr, uint32_t r[4]) {
    asm volatile("ldmatrix.sync.aligned.m8n8.x4.shared.b16 {%0,%1,%2,%3}, [%4];"
        : "=r"(r[0]), "=r"(r[1]), "=r"(r[2]), "=r"(r[3]) : "r"(addr));
}
__device__ __forceinline__ void cp16(uint32_t saddr, const void* g) {
    asm volatile("cp.async.cg.shared.global [%0], [%1], 16;" :: "r"(saddr), "l"(g));
}
#define CP_COMMIT() asm volatile("cp.async.commit_group;" ::: "memory")
#define CP_WAIT1()  asm volatile("cp.async.wait_group 1;" ::: "memory")
#define CP_WAIT0()  asm volatile("cp.async.wait_group 0;" ::: "memory")

// ---------------------------------------------------------------------------
// Fused split: x + 4 weight matrices -> bf16 hi/lo, one launch.
// Virtual concat over float4 indices; every 256-thread block is segment-uniform.
// ---------------------------------------------------------------------------
#define N4_X (M_ROWS * D_MODEL / 4)      // 2097152
#define N4_W (D_MODEL * D_MODEL / 4)     // 262144

__device__ __forceinline__ void split_store(const float* __restrict__ src,
                                            __nv_bfloat16* __restrict__ hi,
                                            __nv_bfloat16* __restrict__ lo, int i)
{
    float4 v = reinterpret_cast<const float4*>(src)[i];
    __nv_bfloat16 h0 = __float2bfloat16(v.x);
    __nv_bfloat16 h1 = __float2bfloat16(v.y);
    __nv_bfloat16 h2 = __float2bfloat16(v.z);
    __nv_bfloat16 h3 = __float2bfloat16(v.w);
    reinterpret_cast<__nv_bfloat162*>(hi)[2 * i]     = __halves2bfloat162(h0, h1);
    reinterpret_cast<__nv_bfloat162*>(hi)[2 * i + 1] = __halves2bfloat162(h2, h3);
    __nv_bfloat16 l0 = __float2bfloat16(v.x - __bfloat162float(h0));
    __nv_bfloat16 l1 = __float2bfloat16(v.y - __bfloat162float(h1));
    __nv_bfloat16 l2 = __float2bfloat16(v.z - __bfloat162float(h2));
    __nv_bfloat16 l3 = __float2bfloat16(v.w - __bfloat162float(h3));
    reinterpret_cast<__nv_bfloat162*>(lo)[2 * i]     = __halves2bfloat162(l0, l1);
    reinterpret_cast<__nv_bfloat162*>(lo)[2 * i + 1] = __halves2bfloat162(l2, l3);
}

__global__ void split_all(const float* __restrict__ x,
                          const float* __restrict__ Wq, const float* __restrict__ Wk,
                          const float* __restrict__ Wv, const float* __restrict__ Wo,
                          __nv_bfloat16* __restrict__ xhi, __nv_bfloat16* __restrict__ xlo,
                          __nv_bfloat16* __restrict__ whi, __nv_bfloat16* __restrict__ wlo)
{
    int i = blockIdx.x * blockDim.x + threadIdx.x;
    if (i < N4_X) {
        split_store(x, xhi, xlo, i);
    } else {
        int j = i - N4_X;
        int w = j >> 18;              // 0..3 (N4_W = 2^18)
        int o = j & (N4_W - 1);
        const float* src = (w == 0) ? Wq : (w == 1) ? Wk : (w == 2) ? Wv : Wo;
        size_t woff = (size_t)w * D_MODEL * D_MODEL;   // element offset
        split_store(src, whi + woff, wlo + woff, o);
    }
}

// ---------------------------------------------------------------------------
// GEMM: C[8192,1024] = A @ W^T + bias.  bf16x2 split, mma.m16n8k16, fp32 acc.
// CTA tile 128x128, BK=32 (64B rows, SW64 swizzle), 3-stage cp.async pipeline,
// 256 threads (8 warps, 4x2, warp tile 32x64).  96KB smem -> 2 CTAs/SM.
// blockIdx.z selects weight/bias/output set (fused QKV); z>=1 outputs (K,V)
// are tf32-rounded in the epilogue so flash can consume them without cvt.
// ---------------------------------------------------------------------------
#define NSLAB 32                   // K / 32
#define AHI_OFF 0
#define ALO_OFF 8192
#define BHI_OFF 16384
#define BLO_OFF 24576
#define STAGE_B 32768
#define G_SMEM (3 * STAGE_B)       // 98304 -> occupancy 2

__global__ __launch_bounds__(256, 2)
void gemm_bf16x2(const __nv_bfloat16* __restrict__ Ahi, const __nv_bfloat16* __restrict__ Alo,
                 const __nv_bfloat16* __restrict__ WhiB, const __nv_bfloat16* __restrict__ WloB,
                 const float* __restrict__ bias0, const float* __restrict__ bias1,
                 const float* __restrict__ bias2,
                 float* __restrict__ C0, float* __restrict__ C1, float* __restrict__ C2)
{
    extern __shared__ char smem[];
    const uint32_t sb = smem_u32(smem);
    const int tid = threadIdx.x, lane = tid & 31, warp = tid >> 5;
    const int g = lane >> 2, t = lane & 3;
    const int wm = warp >> 1, wn = warp & 1;
    const int m0 = blockIdx.y * 128, n0 = blockIdx.x * 128;
    const int z = blockIdx.z;

    const __nv_bfloat16* Bhi = WhiB + (size_t)z * D_MODEL * D_MODEL;
    const __nv_bfloat16* Blo = WloB + (size_t)z * D_MODEL * D_MODEL;
    const float* bias = (z == 0) ? bias0 : (z == 1) ? bias1 : bias2;
    float* C = (z == 0) ? C0 : (z == 1) ? C1 : C2;
    const bool do_round = (z >= 1);       // K,V consumed by flash as tf32

    // stage load: BK=32 -> 64B rows, SW64 swizzle. 8 cp16/thread/slab.
    auto load_slab = [&](int slab, int stage) {
        const uint32_t st = sb + stage * STAGE_B;
        const int kbyte = slab * 64;               // 32 bf16 = 64 bytes
#pragma unroll
        for (int i = 0; i < 2; i++) {
            int idx = tid + i * 256;               // 0..511
            int r = idx >> 2, c = idx & 3;         // r 0..127, c 0..3 (16B chunks)
            uint32_t off = r * 64 + c * 16;
            uint32_t sw = off ^ ((off >> 3) & 0x30);
            size_t ga = (size_t)(m0 + r) * 2048 + kbyte + c * 16;
            cp16(st + AHI_OFF + sw, (const char*)Ahi + ga);
            cp16(st + ALO_OFF + sw, (const char*)Alo + ga);
            size_t gb = (size_t)(n0 + r) * 2048 + kbyte + c * 16;
            cp16(st + BHI_OFF + sw, (const char*)Bhi + gb);
            cp16(st + BLO_OFF + sw, (const char*)Blo + gb);
        }
    };

    float acc[2][8][4];
#pragma unroll
    for (int i = 0; i < 2; i++)
#pragma unroll
        for (int j = 0; j < 8; j++)
#pragma unroll
            for (int e = 0; e < 4; e++) acc[i][j][e] = 0.f;

    load_slab(0, 0); CP_COMMIT();
    load_slab(1, 1); CP_COMMIT();

    const int lr  = lane & 7;
    const int aR8 = ((lane >> 3) & 1) * 8;
    const int aCh = (lane >> 4);
    const int bR8 = (lane >> 4) * 8;
    const int bCh = (lane >> 3) & 1;

    for (int it = 0; it < NSLAB; it++) {
        const int s = it % 3;
        if (it == NSLAB - 1) { CP_WAIT0(); } else { CP_WAIT1(); }
        __syncthreads();

        const uint32_t stA_h = sb + s * STAGE_B + AHI_OFF;
        const uint32_t stA_l = sb + s * STAGE_B + ALO_OFF;
        const uint32_t stB_h = sb + s * STAGE_B + BHI_OFF;
        const uint32_t stB_l = sb + s * STAGE_B + BLO_OFF;

#pragma unroll
        for (int ks = 0; ks < 2; ks++) {
            uint32_t ah[2][4], al[2][4];
#pragma unroll
            for (int mt = 0; mt < 2; mt++) {
                int row = wm * 32 + mt * 16 + aR8 + lr;
                int ch  = ks * 2 + aCh;
                uint32_t off = row * 64 + ch * 16;
                uint32_t sw = off ^ ((off >> 3) & 0x30);
                ldsm4(stA_h + sw, ah[mt]);
                ldsm4(stA_l + sw, al[mt]);
            }
            uint32_t bh[4][4], bl[4][4];
#pragma unroll
            for (int np = 0; np < 4; np++) {
                int row = wn * 64 + np * 16 + bR8 + lr;
                int ch  = ks * 2 + bCh;
                uint32_t off = row * 64 + ch * 16;
                uint32_t sw = off ^ ((off >> 3) & 0x30);
                ldsm4(stB_h + sw, bh[np]);
                ldsm4(stB_l + sw, bl[np]);
            }
#pragma unroll
            for (int mt = 0; mt < 2; mt++) {
#pragma unroll
                for (int nf = 0; nf < 8; nf++) {
                    uint32_t b0h = bh[nf >> 1][(nf & 1) * 2];
                    uint32_t b1h = bh[nf >> 1][(nf & 1) * 2 + 1];
                    uint32_t b0l = bl[nf >> 1][(nf & 1) * 2];
                    uint32_t b1l = bl[nf >> 1][(nf & 1) * 2 + 1];
                    mma16(acc[mt][nf], ah[mt], b0h, b1h);
                    mma16(acc[mt][nf], ah[mt], b0l, b1l);
                    mma16(acc[mt][nf], al[mt], b0h, b1h);
                }
            }
        }
        __syncthreads();
        if (it + 2 < NSLAB) { load_slab(it + 2, (it + 2) % 3); CP_COMMIT(); }
    }

#pragma unroll
    for (int mt = 0; mt < 2; mt++) {
#pragma unroll
        for (int nf = 0; nf < 8; nf++) {
            int col = n0 + wn * 64 + nf * 8 + 2 * t;
            float b0v = bias[col], b1v = bias[col + 1];
            int row0 = m0 + wm * 32 + mt * 16 + g;
            float v00 = acc[mt][nf][0] + b0v, v01 = acc[mt][nf][1] + b1v;
            float v10 = acc[mt][nf][2] + b0v, v11 = acc[mt][nf][3] + b1v;
            if (do_round) {
                v00 = tf32r(v00); v01 = tf32r(v01);
                v10 = tf32r(v10); v11 = tf32r(v11);
            }
            *reinterpret_cast<float2*>(&C[(size_t)row0 * D_MODEL + col]) = make_float2(v00, v01);
            *reinterpret_cast<float2*>(&C[(size_t)(row0 + 8) * D_MODEL + col]) = make_float2(v10, v11);
        }
    }
}

// ---------------------------------------------------------------------------
// Flash attention v3: tf32 mma, Q-block 128 rows, K-tile 64, 4 warps.
// K/V arrive pre-tf32-rounded -> staged with cp.async into double-buffered
// smem, prefetch overlapped with previous tile's compute. Epilogue writes
// bf16 hi/lo directly (feeds the O projection without a split pass).
// ---------------------------------------------------------------------------
#define KPAD 68
#define VPAD 72
#define PPAD 68
#define FL_SMEM ((2 * 64 * KPAD + 2 * 64 * VPAD + 128 * PPAD) * 4)   // 106496

__global__ __launch_bounds__(128, 2)
void flash_tf32(const float* __restrict__ Q, const float* __restrict__ Kg,
                const float* __restrict__ Vg,
                __nv_bfloat16* __restrict__ Ohi, __nv_bfloat16* __restrict__ Olo)
{
    extern __shared__ float sm[];
    float* KsB = sm;                          // 2 x 64 x KPAD
    float* VsB = sm + 2 * 64 * KPAD;          // 2 x 64 x VPAD
    float* Ps  = sm + 2 * 64 * KPAD + 2 * 64 * VPAD;   // 128 x PPAD
    const uint32_t ks_u32 = smem_u32(KsB);
    const uint32_t vs_u32 = smem_u32(VsB);

    const int tid  = threadIdx.x;
    const int lane = tid & 31;
    const int warp = tid >> 5;          // 0..3
    const int g = lane >> 2, t = lane & 3;

    const int qb = 15 - blockIdx.x;
    const int qstart = qb * 128;
    const int bh = blockIdx.y;
    const int b = bh >> 4;
    const int h = bh & 15;
    const int rowbase = b * T_SEQ;
    const int hoff = h * D_HEAD;

    // prefetch K/V tile kt into buffer buf (pure 16B async copies; 8+8/thread)
    auto prefetch = [&](int kt, int buf) {
        const int kb = kt * 64;
        const float* Kbase = Kg + (size_t)(rowbase + kb) * D_MODEL + hoff;
        const float* Vbase = Vg + (size_t)(rowbase + kb) * D_MODEL + hoff;
        const uint32_t kd = ks_u32 + buf * 64 * KPAD * 4;
        const uint32_t vd = vs_u32 + buf * 64 * VPAD * 4;
#pragma unroll
        for (int i = 0; i < 8; i++) {
            int idx = tid + i * 128;       // 0..1023
            int row = idx >> 4;
            int c   = idx & 15;            // 16B chunk in row
            cp16(kd + (uint32_t)(row * KPAD + c * 4) * 4, Kbase + (size_t)row * D_MODEL + c * 4);
            cp16(vd + (uint32_t)(row * VPAD + c * 4) * 4, Vbase + (size_t)row * D_MODEL + c * 4);
        }
    };

    prefetch(0, 0); CP_COMMIT();

    // Q fragments (pre-scaled for exp2 domain), registers for all tiles
    const float qs = 0.125f * 1.4426950408889634f;
    unsigned qa[2][8][4];
#pragma unroll
    for (int mt = 0; mt < 2; mt++) {
        int r0 = rowbase + qstart + warp * 32 + mt * 16 + g;
#pragma unroll
        for (int kf = 0; kf < 8; kf++) {
            int colx = hoff + kf * 8 + t;
            qa[mt][kf][0] = f2tf32(qs * Q[(size_t)r0 * D_MODEL + colx]);
            qa[mt][kf][1] = f2tf32(qs * Q[(size_t)(r0 + 8) * D_MODEL + colx]);
            qa[mt][kf][2] = f2tf32(qs * Q[(size_t)r0 * D_MODEL + colx + 4]);
            qa[mt][kf][3] = f2tf32(qs * Q[(size_t)(r0 + 8) * D_MODEL + colx + 4]);
        }
    }

    float o[2][8][4];
#pragma unroll
    for (int mt = 0; mt < 2; mt++)
#pragma unroll
        for (int nf = 0; nf < 8; nf++)
#pragma unroll
            for (int e = 0; e < 4; e++) o[mt][nf][e] = 0.f;
    float mr[2][2], lsum[2][2];
#pragma unroll
    for (int mt = 0; mt < 2; mt++) {
        mr[mt][0] = -INFINITY; mr[mt][1] = -INFINITY;
        lsum[mt][0] = 0.f; lsum[mt][1] = 0.f;
    }

    const int ktmax = 2 * qb + 1;
    for (int kt = 0; kt <= ktmax; kt++) {
        const int kb = kt * 64;
        const int buf = kt & 1;

        if (kt < ktmax) { prefetch(kt + 1, buf ^ 1); CP_COMMIT(); CP_WAIT1(); }
        else            { CP_WAIT0(); }
        __syncthreads();

        const float* Ks = KsB + buf * 64 * KPAD;
        const float* Vs = VsB + buf * 64 * VPAD;

        // ---- S = Q @ K^T : B fragment loaded once, used by both m-tiles ----
        float s[2][8][4];
#pragma unroll
        for (int mt = 0; mt < 2; mt++)
#pragma unroll
            for (int nf = 0; nf < 8; nf++)
#pragma unroll
                for (int e = 0; e < 4; e++) s[mt][nf][e] = 0.f;

#pragma unroll
        for (int kf = 0; kf < 8; kf++) {
#pragma unroll
            for (int nf = 0; nf < 8; nf++) {
                unsigned b0 = __float_as_uint(Ks[(nf * 8 + g) * KPAD + kf * 8 + t]);
                unsigned b1 = __float_as_uint(Ks[(nf * 8 + g) * KPAD + kf * 8 + t + 4]);
                mma8(s[0][nf], qa[0][kf], b0, b1);
                mma8(s[1][nf], qa[1][kf], b0, b1);
            }
        }

        if (kt >= 2 * qb) {
#pragma unroll
            for (int mt = 0; mt < 2; mt++) {
                int rb = qstart + warp * 32 + mt * 16 + g;
#pragma unroll
                for (int nf = 0; nf < 8; nf++) {
                    int c0 = kb + nf * 8 + 2 * t;
                    if (c0     > rb)     s[mt][nf][0] = -INFINITY;
                    if (c0 + 1 > rb)     s[mt][nf][1] = -INFINITY;
                    if (c0     > rb + 8) s[mt][nf][2] = -INFINITY;
                    if (c0 + 1 > rb + 8) s[mt][nf][3] = -INFINITY;
                }
            }
        }

        // ---- online softmax per m-tile ----
#pragma unroll
        for (int mt = 0; mt < 2; mt++) {
            float mx0 = -INFINITY, mx1 = -INFINITY;
#pragma unroll
            for (int nf = 0; nf < 8; nf++) {
                mx0 = fmaxf(mx0, fmaxf(s[mt][nf][0], s[mt][nf][1]));
                mx1 = fmaxf(mx1, fmaxf(s[mt][nf][2], s[mt][nf][3]));
            }
            mx0 = fmaxf(mx0, __shfl_xor_sync(0xffffffffu, mx0, 1));
            mx0 = fmaxf(mx0, __shfl_xor_sync(0xffffffffu, mx0, 2));
            mx1 = fmaxf(mx1, __shfl_xor_sync(0xffffffffu, mx1, 1));
            mx1 = fmaxf(mx1, __shfl_xor_sync(0xffffffffu, mx1, 2));

            float mn0 = fmaxf(mr[mt][0], mx0), mn1 = fmaxf(mr[mt][1], mx1);
            float corr0 = ex2f(mr[mt][0] - mn0), corr1 = ex2f(mr[mt][1] - mn1);
            float sum0 = 0.f, sum1 = 0.f;
#pragma unroll
            for (int nf = 0; nf < 8; nf++) {
                s[mt][nf][0] = ex2f(s[mt][nf][0] - mn0); sum0 += s[mt][nf][0];
                s[mt][nf][1] = ex2f(s[mt][nf][1] - mn0); sum0 += s[mt][nf][1];
                s[mt][nf][2] = ex2f(s[mt][nf][2] - mn1); sum1 += s[mt][nf][2];
                s[mt][nf][3] = ex2f(s[mt][nf][3] - mn1); sum1 += s[mt][nf][3];
            }
            sum0 += __shfl_xor_sync(0xffffffffu, sum0, 1);
            sum0 += __shfl_xor_sync(0xffffffffu, sum0, 2);
            sum1 += __shfl_xor_sync(0xffffffffu, sum1, 1);
            sum1 += __shfl_xor_sync(0xffffffffu, sum1, 2);

            lsum[mt][0] = lsum[mt][0] * corr0 + sum0;  mr[mt][0] = mn0;
            lsum[mt][1] = lsum[mt][1] * corr1 + sum1;  mr[mt][1] = mn1;
#pragma unroll
            for (int nf = 0; nf < 8; nf++) {
                o[mt][nf][0] *= corr0; o[mt][nf][1] *= corr0;
                o[mt][nf][2] *= corr1; o[mt][nf][3] *= corr1;
            }

            int pr0 = warp * 32 + mt * 16 + g;
#pragma unroll
            for (int nf = 0; nf < 8; nf++) {
                int pc = nf * 8 + 2 * t;
                Ps[pr0 * PPAD + pc]           = __uint_as_float(f2tf32(s[mt][nf][0]));
                Ps[pr0 * PPAD + pc + 1]       = __uint_as_float(f2tf32(s[mt][nf][1]));
                Ps[(pr0 + 8) * PPAD + pc]     = __uint_as_float(f2tf32(s[mt][nf][2]));
                Ps[(pr0 + 8) * PPAD + pc + 1] = __uint_as_float(f2tf32(s[mt][nf][3]));
            }
        }
        __syncwarp();

        // ---- O += P @ V : V fragment loaded once, used by both m-tiles ----
#pragma unroll
        for (int kf = 0; kf < 8; kf++) {
            unsigned pa[2][4];
#pragma unroll
            for (int mt = 0; mt < 2; mt++) {
                int pr = warp * 32 + mt * 16 + g;
                pa[mt][0] = __float_as_uint(Ps[pr * PPAD + kf * 8 + t]);
                pa[mt][1] = __float_as_uint(Ps[(pr + 8) * PPAD + kf * 8 + t]);
                pa[mt][2] = __float_as_uint(Ps[pr * PPAD + kf * 8 + t + 4]);
                pa[mt][3] = __float_as_uint(Ps[(pr + 8) * PPAD + kf * 8 + t + 4]);
            }
#pragma unroll
            for (int nf = 0; nf < 8; nf++) {
                unsigned b0 = __float_as_uint(Vs[(kf * 8 + t) * VPAD + nf * 8 + g]);
                unsigned b1 = __float_as_uint(Vs[(kf * 8 + t + 4) * VPAD + nf * 8 + g]);
                mma8(o[0][nf], pa[0], b0, b1);
                mma8(o[1][nf], pa[1], b0, b1);
            }
        }
        __syncthreads();   // protect buffers: next iter's prefetch reuses buf^1
    }

    // ---- finalize: write bf16 hi/lo directly (feeds O projection) ----
#pragma unroll
    for (int mt = 0; mt < 2; mt++) {
        float inv0 = 1.0f / lsum[mt][0], inv1 = 1.0f / lsum[mt][1];
        int ro0 = rowbase + qstart + warp * 32 + mt * 16 + g;
#pragma unroll
        for (int nf = 0; nf < 8; nf++) {
            int colx = hoff + nf * 8 + 2 * t;
            float v00 = o[mt][nf][0] * inv0, v01 = o[mt][nf][1] * inv0;
            float v10 = o[mt][nf][2] * inv1, v11 = o[mt][nf][3] * inv1;
            __nv_bfloat16 h00 = __float2bfloat16(v00), h01 = __float2bfloat16(v01);
            __nv_bfloat16 h10 = __float2bfloat16(v10), h11 = __float2bfloat16(v11);
            *reinterpret_cast<__nv_bfloat162*>(&Ohi[(size_t)ro0 * D_MODEL + colx]) =
                __halves2bfloat162(h00, h01);
            *reinterpret_cast<__nv_bfloat162*>(&Ohi[(size_t)(ro0 + 8) * D_MODEL + colx]) =
                __halves2bfloat162(h10, h11);
            __nv_bfloat16 l00 = __float2bfloat16(v00 - __bfloat162float(h00));
            __nv_bfloat16 l01 = __float2bfloat16(v01 - __bfloat162float(h01));
            __nv_bfloat16 l10 = __float2bfloat16(v10 - __bfloat162float(h10));
            __nv_bfloat16 l11 = __float2bfloat16(v11 - __bfloat162float(h11));
            *reinterpret_cast<__nv_bfloat162*>(&Olo[(size_t)ro0 * D_MODEL + colx]) =
                __halves2bfloat162(l00, l01);
            *reinterpret_cast<__nv_bfloat162*>(&Olo[(size_t)(ro0 + 8) * D_MODEL + colx]) =
                __halves2bfloat162(l10, l11);
        }
    }
}

// ---------------------------------------------------------------------------
// Launch
// ---------------------------------------------------------------------------
extern "C" void kernel_launch(void* const* d_in, const int* in_sizes, int n_in,
                              void* d_out, int out_size)
{
    const float* x  = (const float*)d_in[0];
    const float* Wq = (const float*)d_in[1];
    const float* bq = (const float*)d_in[2];
    const float* Wk = (const float*)d_in[3];
    const float* bk = (const float*)d_in[4];
    const float* Wv = (const float*)d_in[5];
    const float* bv = (const float*)d_in[6];
    const float* Wo = (const float*)d_in[7];
    const float* bo = (const float*)d_in[8];
    float* out = (float*)d_out;

    float *Qb, *Kb, *Vb;
    __nv_bfloat16 *xhi, *xlo, *ohi, *olo, *whi, *wlo;
    cudaGetSymbolAddress((void**)&Qb, g_Q);
    cudaGetSymbolAddress((void**)&Kb, g_K);
    cudaGetSymbolAddress((void**)&Vb, g_V);
    cudaGetSymbolAddress((void**)&xhi, g_xhi);
    cudaGetSymbolAddress((void**)&xlo, g_xlo);
    cudaGetSymbolAddress((void**)&ohi, g_ohi);
    cudaGetSymbolAddress((void**)&olo, g_olo);
    cudaGetSymbolAddress((void**)&whi, g_whi);
    cudaGetSymbolAddress((void**)&wlo, g_wlo);

    cudaFuncSetAttribute(gemm_bf16x2, cudaFuncAttributeMaxDynamicSharedMemorySize, G_SMEM);
    cudaFuncSetAttribute(flash_tf32, cudaFuncAttributeMaxDynamicSharedMemorySize, FL_SMEM);

    const size_t wstep = (size_t)D_MODEL * D_MODEL;
    const int n4total = N4_X + 4 * N4_W;          // 3145728

    split_all<<<n4total / 256, 256>>>(x, Wq, Wk, Wv, Wo, xhi, xlo, whi, wlo);

    dim3 qkvgrid(D_MODEL / 128, M_ROWS / 128, 3);   // (8, 64, 3)
    gemm_bf16x2<<<qkvgrid, 256, G_SMEM>>>(xhi, xlo, whi, wlo, bq, bk, bv, Qb, Kb, Vb);

    dim3 fgrid(T_SEQ / 128, B_SZ * N_HEADS);        // (16, 64)
    flash_tf32<<<fgrid, 128, FL_SMEM>>>(Qb, Kb, Vb, ohi, olo);

    dim3 ogrid(D_MODEL / 128, M_ROWS / 128, 1);     // (8, 64, 1)
    gemm_bf16x2<<<ogrid, 256, G_SMEM>>>(ohi, olo, whi + 3 * wstep, wlo + 3 * wstep,
                                        bo, bo, bo, out, out, out);
}

// round 7
// speedup vs baseline: 7.4955x; 1.2572x over previous
#include <cuda_runtime.h>
#include <cuda_bf16.h>
#include <cuda_fp16.h>
#include <math.h>
#include <stdint.h>

#define D_MODEL 1024
#define N_HEADS 16
#define D_HEAD  64
#define B_SZ    4
#define T_SEQ   2048
#define M_ROWS  (B_SZ * T_SEQ)   // 8192

// ---------------- scratch (allocation-free rule: __device__ globals) --------
__device__ __half g_Qh[M_ROWS * D_MODEL];
__device__ __half g_Kh[M_ROWS * D_MODEL];
__device__ __half g_Vt[B_SZ * N_HEADS * D_HEAD * T_SEQ];   // [bh][dim][tok]
__device__ __nv_bfloat16 g_xhi[M_ROWS * D_MODEL];
__device__ __nv_bfloat16 g_xlo[M_ROWS * D_MODEL];
__device__ __nv_bfloat16 g_ohi[M_ROWS * D_MODEL];
__device__ __nv_bfloat16 g_olo[M_ROWS * D_MODEL];
__device__ __nv_bfloat16 g_whi[4 * D_MODEL * D_MODEL];
__device__ __nv_bfloat16 g_wlo[4 * D_MODEL * D_MODEL];

// ---------------- PTX helpers (all sm_80-compatible) ------------------------
__device__ __forceinline__ uint32_t smem_u32(const void* p) {
    uint32_t a;
    asm("{ .reg .u64 t; cvta.to.shared.u64 t, %1; cvt.u32.u64 %0, t; }" : "=r"(a) : "l"(p));
    return a;
}
__device__ __forceinline__ float ex2f(float x) {
    float y; asm("ex2.approx.f32 %0, %1;" : "=f"(y) : "f"(x)); return y;
}
__device__ __forceinline__ void mma16(float c[4], const uint32_t a[4], uint32_t b0, uint32_t b1) {
    asm("mma.sync.aligned.m16n8k16.row.col.f32.bf16.bf16.f32 "
        "{%0,%1,%2,%3}, {%4,%5,%6,%7}, {%8,%9}, {%0,%1,%2,%3};"
        : "+f"(c[0]), "+f"(c[1]), "+f"(c[2]), "+f"(c[3])
        : "r"(a[0]), "r"(a[1]), "r"(a[2]), "r"(a[3]), "r"(b0), "r"(b1));
}
__device__ __forceinline__ void mma16h(float c[4], const uint32_t a[4], uint32_t b0, uint32_t b1) {
    asm("mma.sync.aligned.m16n8k16.row.col.f32.f16.f16.f32 "
        "{%0,%1,%2,%3}, {%4,%5,%6,%7}, {%8,%9}, {%0,%1,%2,%3};"
        : "+f"(c[0]), "+f"(c[1]), "+f"(c[2]), "+f"(c[3])
        : "r"(a[0]), "r"(a[1]), "r"(a[2]), "r"(a[3]), "r"(b0), "r"(b1));
}
__device__ __forceinline__ void ldsm4(uint32_t addr, uint32_t r[4]) {
    asm volatile("ldmatrix.sync.aligned.m8n8.x4.shared.b16 {%0,%1,%2,%3}, [%4];"
        : "=r"(r[0]), "=r"(r[1]), "=r"(r[2]), "=r"(r[3]) : "r"(addr));
}
__device__ __forceinline__ void cp16(uint32_t saddr, const void* g) {
    asm volatile("cp.async.cg.shared.global [%0], [%1], 16;" :: "r"(saddr), "l"(g));
}
#define CP_COMMIT() asm volatile("cp.async.commit_group;" ::: "memory")
#define CP_WAIT1()  asm volatile("cp.async.wait_group 1;" ::: "memory")
#define CP_WAIT0()  asm volatile("cp.async.wait_group 0;" ::: "memory")

// ---------------------------------------------------------------------------
// Fused split: x + 4 weight matrices -> bf16 hi/lo, one launch.
// ---------------------------------------------------------------------------
#define N4_X (M_ROWS * D_MODEL / 4)      // 2097152
#define N4_W (D_MODEL * D_MODEL / 4)     // 262144

__device__ __forceinline__ void split_store(const float* __restrict__ src,
                                            __nv_bfloat16* __restrict__ hi,
                                            __nv_bfloat16* __restrict__ lo, int i)
{
    float4 v = reinterpret_cast<const float4*>(src)[i];
    __nv_bfloat16 h0 = __float2bfloat16(v.x);
    __nv_bfloat16 h1 = __float2bfloat16(v.y);
    __nv_bfloat16 h2 = __float2bfloat16(v.z);
    __nv_bfloat16 h3 = __float2bfloat16(v.w);
    reinterpret_cast<__nv_bfloat162*>(hi)[2 * i]     = __halves2bfloat162(h0, h1);
    reinterpret_cast<__nv_bfloat162*>(hi)[2 * i + 1] = __halves2bfloat162(h2, h3);
    __nv_bfloat16 l0 = __float2bfloat16(v.x - __bfloat162float(h0));
    __nv_bfloat16 l1 = __float2bfloat16(v.y - __bfloat162float(h1));
    __nv_bfloat16 l2 = __float2bfloat16(v.z - __bfloat162float(h2));
    __nv_bfloat16 l3 = __float2bfloat16(v.w - __bfloat162float(h3));
    reinterpret_cast<__nv_bfloat162*>(lo)[2 * i]     = __halves2bfloat162(l0, l1);
    reinterpret_cast<__nv_bfloat162*>(lo)[2 * i + 1] = __halves2bfloat162(l2, l3);
}

__global__ void split_all(const float* __restrict__ x,
                          const float* __restrict__ Wq, const float* __restrict__ Wk,
                          const float* __restrict__ Wv, const float* __restrict__ Wo,
                          __nv_bfloat16* __restrict__ xhi, __nv_bfloat16* __restrict__ xlo,
                          __nv_bfloat16* __restrict__ whi, __nv_bfloat16* __restrict__ wlo)
{
    int i = blockIdx.x * blockDim.x + threadIdx.x;
    if (i < N4_X) {
        split_store(x, xhi, xlo, i);
    } else {
        int j = i - N4_X;
        int w = j >> 18;
        int o = j & (N4_W - 1);
        const float* src = (w == 0) ? Wq : (w == 1) ? Wk : (w == 2) ? Wv : Wo;
        size_t woff = (size_t)w * D_MODEL * D_MODEL;
        split_store(src, whi + woff, wlo + woff, o);
    }
}

// ---------------------------------------------------------------------------
// GEMM: bf16x2 split (3 mma), fp32 acc. CTA 128x128, BK=32, 3-stage cp.async.
// mode=1 (QKV): z=0 -> fp16 scaled Q; z=1 -> fp16 K; z=2 -> fp16 V^T scatter.
// mode=0 (O):   fp32 output + bias.
// ---------------------------------------------------------------------------
#define NSLAB 32
#define AHI_OFF 0
#define ALO_OFF 8192
#define BHI_OFF 16384
#define BLO_OFF 24576
#define STAGE_B 32768
#define G_SMEM (3 * STAGE_B)
#define QSCALE 0.18033688f            // (1/8) * log2(e)

__global__ __launch_bounds__(256, 2)
void gemm_bf16x2(const __nv_bfloat16* __restrict__ Ahi, const __nv_bfloat16* __restrict__ Alo,
                 const __nv_bfloat16* __restrict__ WhiB, const __nv_bfloat16* __restrict__ WloB,
                 const float* __restrict__ bias0, const float* __restrict__ bias1,
                 const float* __restrict__ bias2, int mode,
                 __half* __restrict__ Qh, __half* __restrict__ Kh, __half* __restrict__ Vt,
                 float* __restrict__ Co)
{
    extern __shared__ char smem[];
    const uint32_t sb = smem_u32(smem);
    const int tid = threadIdx.x, lane = tid & 31, warp = tid >> 5;
    const int g = lane >> 2, t = lane & 3;
    const int wm = warp >> 1, wn = warp & 1;
    const int m0 = blockIdx.y * 128, n0 = blockIdx.x * 128;
    const int z = blockIdx.z;

    const __nv_bfloat16* Bhi = WhiB + (size_t)z * D_MODEL * D_MODEL;
    const __nv_bfloat16* Blo = WloB + (size_t)z * D_MODEL * D_MODEL;
    const float* bias = (z == 0) ? bias0 : (z == 1) ? bias1 : bias2;

    auto load_slab = [&](int slab, int stage) {
        const uint32_t st = sb + stage * STAGE_B;
        const int kbyte = slab * 64;
#pragma unroll
        for (int i = 0; i < 2; i++) {
            int idx = tid + i * 256;
            int r = idx >> 2, c = idx & 3;
            uint32_t off = r * 64 + c * 16;
            uint32_t sw = off ^ ((off >> 3) & 0x30);
            size_t ga = (size_t)(m0 + r) * 2048 + kbyte + c * 16;
            cp16(st + AHI_OFF + sw, (const char*)Ahi + ga);
            cp16(st + ALO_OFF + sw, (const char*)Alo + ga);
            size_t gb = (size_t)(n0 + r) * 2048 + kbyte + c * 16;
            cp16(st + BHI_OFF + sw, (const char*)Bhi + gb);
            cp16(st + BLO_OFF + sw, (const char*)Blo + gb);
        }
    };

    float acc[2][8][4];
#pragma unroll
    for (int i = 0; i < 2; i++)
#pragma unroll
        for (int j = 0; j < 8; j++)
#pragma unroll
            for (int e = 0; e < 4; e++) acc[i][j][e] = 0.f;

    load_slab(0, 0); CP_COMMIT();
    load_slab(1, 1); CP_COMMIT();

    const int lr  = lane & 7;
    const int aR8 = ((lane >> 3) & 1) * 8;
    const int aCh = (lane >> 4);
    const int bR8 = (lane >> 4) * 8;
    const int bCh = (lane >> 3) & 1;

    for (int it = 0; it < NSLAB; it++) {
        const int s = it % 3;
        if (it == NSLAB - 1) { CP_WAIT0(); } else { CP_WAIT1(); }
        __syncthreads();

        const uint32_t stA_h = sb + s * STAGE_B + AHI_OFF;
        const uint32_t stA_l = sb + s * STAGE_B + ALO_OFF;
        const uint32_t stB_h = sb + s * STAGE_B + BHI_OFF;
        const uint32_t stB_l = sb + s * STAGE_B + BLO_OFF;

#pragma unroll
        for (int ks = 0; ks < 2; ks++) {
            uint32_t ah[2][4], al[2][4];
#pragma unroll
            for (int mt = 0; mt < 2; mt++) {
                int row = wm * 32 + mt * 16 + aR8 + lr;
                int ch  = ks * 2 + aCh;
                uint32_t off = row * 64 + ch * 16;
                uint32_t sw = off ^ ((off >> 3) & 0x30);
                ldsm4(stA_h + sw, ah[mt]);
                ldsm4(stA_l + sw, al[mt]);
            }
            uint32_t bh[4][4], bl[4][4];
#pragma unroll
            for (int np = 0; np < 4; np++) {
                int row = wn * 64 + np * 16 + bR8 + lr;
                int ch  = ks * 2 + bCh;
                uint32_t off = row * 64 + ch * 16;
                uint32_t sw = off ^ ((off >> 3) & 0x30);
                ldsm4(stB_h + sw, bh[np]);
                ldsm4(stB_l + sw, bl[np]);
            }
#pragma unroll
            for (int mt = 0; mt < 2; mt++) {
#pragma unroll
                for (int nf = 0; nf < 8; nf++) {
                    uint32_t b0h = bh[nf >> 1][(nf & 1) * 2];
                    uint32_t b1h = bh[nf >> 1][(nf & 1) * 2 + 1];
                    uint32_t b0l = bl[nf >> 1][(nf & 1) * 2];
                    uint32_t b1l = bl[nf >> 1][(nf & 1) * 2 + 1];
                    mma16(acc[mt][nf], ah[mt], b0h, b1h);
                    mma16(acc[mt][nf], ah[mt], b0l, b1l);
                    mma16(acc[mt][nf], al[mt], b0h, b1h);
                }
            }
        }
        // NOTE: no second __syncthreads needed — next loads target stage
        // (it+2)%3, disjoint from the stages being read this iteration.
        if (it + 2 < NSLAB) { load_slab(it + 2, (it + 2) % 3); CP_COMMIT(); }
    }

#pragma unroll
    for (int mt = 0; mt < 2; mt++) {
#pragma unroll
        for (int nf = 0; nf < 8; nf++) {
            int col = n0 + wn * 64 + nf * 8 + 2 * t;
            float b0v = bias[col], b1v = bias[col + 1];
            int row0 = m0 + wm * 32 + mt * 16 + g;
            float v00 = acc[mt][nf][0] + b0v, v01 = acc[mt][nf][1] + b1v;
            float v10 = acc[mt][nf][2] + b0v, v11 = acc[mt][nf][3] + b1v;
            if (mode == 0) {
                *reinterpret_cast<float2*>(&Co[(size_t)row0 * D_MODEL + col]) = make_float2(v00, v01);
                *reinterpret_cast<float2*>(&Co[(size_t)(row0 + 8) * D_MODEL + col]) = make_float2(v10, v11);
            } else if (z == 0) {
                *reinterpret_cast<__half2*>(&Qh[(size_t)row0 * D_MODEL + col]) =
                    __floats2half2_rn(QSCALE * v00, QSCALE * v01);
                *reinterpret_cast<__half2*>(&Qh[(size_t)(row0 + 8) * D_MODEL + col]) =
                    __floats2half2_rn(QSCALE * v10, QSCALE * v11);
            } else if (z == 1) {
                *reinterpret_cast<__half2*>(&Kh[(size_t)row0 * D_MODEL + col]) =
                    __floats2half2_rn(v00, v01);
                *reinterpret_cast<__half2*>(&Kh[(size_t)(row0 + 8) * D_MODEL + col]) =
                    __floats2half2_rn(v10, v11);
            } else {
                // V^T scatter: Vt[(b*16+h)*64 + d][tok]
                int hh = col >> 6, dd = col & 63;
                int tok = row0 & 2047;
                size_t vbase = (size_t)((row0 >> 11) * 16 + hh) * 64;
                Vt[(vbase + dd) * T_SEQ + tok]         = __float2half(v00);
                Vt[(vbase + dd + 1) * T_SEQ + tok]     = __float2half(v01);
                Vt[(vbase + dd) * T_SEQ + tok + 8]     = __float2half(v10);
                Vt[(vbase + dd + 1) * T_SEQ + tok + 8] = __float2half(v11);
            }
        }
    }
}

// ---------------------------------------------------------------------------
// Flash attention v4: fp16 mma16 + ldmatrix. Q-block 128, K-tile 64, 4 warps.
// Q fp16 pre-scaled (exp2 domain); K fp16 [tok][dim]; V fp16 TRANSPOSED
// [dim][tok] so both K and V B-fragments use the non-trans ldsm pattern.
// K/V double-buffered cp.async; P via fp16 smem + ldsm.
// smem: Qs 16K | Ks 2x8K | Vs 2x8K | Ps 16K = 64KB -> 2 CTAs/SM.
// ---------------------------------------------------------------------------
#define QS_OFF 0
#define KS_OFF 16384
#define VS_OFF 32768
#define PS_OFF 49152
#define FL_SMEM 65536

__global__ __launch_bounds__(128, 2)
void flash_h(const __half* __restrict__ Qh, const __half* __restrict__ Kh,
             const __half* __restrict__ Vt,
             __nv_bfloat16* __restrict__ Ohi, __nv_bfloat16* __restrict__ Olo)
{
    extern __shared__ char fsm[];
    const uint32_t sb = smem_u32(fsm);

    const int tid  = threadIdx.x;
    const int lane = tid & 31;
    const int warp = tid >> 5;          // 0..3
    const int g = lane >> 2, t = lane & 3;
    const int lr  = lane & 7;
    const int aR8 = ((lane >> 3) & 1) * 8;
    const int aCh = (lane >> 4);
    const int bR8 = (lane >> 4) * 8;
    const int bCh = (lane >> 3) & 1;

    const int qb = 15 - blockIdx.x;
    const int qstart = qb * 128;
    const int bh = blockIdx.y;
    const int b = bh >> 4;
    const int h = bh & 15;
    const int rowbase = b * T_SEQ;
    const int hoff = h * D_HEAD;

    // ---- stage Q once (128 rows x 128B, SW128) + prefetch tile 0 ----
#pragma unroll
    for (int i = 0; i < 8; i++) {
        int idx = tid + i * 128;           // 0..1023
        int r = idx >> 3, c = idx & 7;
        uint32_t off = r * 128 + c * 16;
        uint32_t sw = off ^ ((off >> 3) & 0x70);
        cp16(sb + QS_OFF + sw,
             (const char*)Qh + ((size_t)(rowbase + qstart + r) * D_MODEL + hoff) * 2 + c * 16);
    }
    auto prefetch = [&](int kt, int buf) {
#pragma unroll
        for (int i = 0; i < 4; i++) {
            int idx = tid + i * 128;       // 0..511
            int r = idx >> 3, c = idx & 7;
            uint32_t off = r * 128 + c * 16;
            uint32_t sw = off ^ ((off >> 3) & 0x70);
            cp16(sb + KS_OFF + buf * 8192 + sw,
                 (const char*)Kh + ((size_t)(rowbase + kt * 64 + r) * D_MODEL + hoff) * 2 + c * 16);
            cp16(sb + VS_OFF + buf * 8192 + sw,
                 (const char*)Vt + ((size_t)(bh * 64 + r) * T_SEQ + kt * 64) * 2 + c * 16);
        }
    };
    prefetch(0, 0);
    CP_COMMIT();
    CP_WAIT0();
    __syncthreads();

    // ---- Q fragments (registers for whole kernel) ----
    uint32_t qa[2][4][4];
#pragma unroll
    for (int mt = 0; mt < 2; mt++)
#pragma unroll
        for (int kc = 0; kc < 4; kc++) {
            uint32_t off = (uint32_t)(warp * 32 + mt * 16 + aR8 + lr) * 128 + (kc * 2 + aCh) * 16;
            uint32_t sw = off ^ ((off >> 3) & 0x70);
            ldsm4(sb + QS_OFF + sw, qa[mt][kc]);
        }

    float o[2][8][4];
#pragma unroll
    for (int mt = 0; mt < 2; mt++)
#pragma unroll
        for (int nf = 0; nf < 8; nf++)
#pragma unroll
            for (int e = 0; e < 4; e++) o[mt][nf][e] = 0.f;
    float mr[2][2], lsum[2][2];
#pragma unroll
    for (int mt = 0; mt < 2; mt++) {
        mr[mt][0] = -INFINITY; mr[mt][1] = -INFINITY;
        lsum[mt][0] = 0.f; lsum[mt][1] = 0.f;
    }

    const int ktmax = 2 * qb + 1;
    for (int kt = 0; kt <= ktmax; kt++) {
        const int kb = kt * 64;
        const int buf = kt & 1;
        const uint32_t ksb = sb + KS_OFF + buf * 8192;
        const uint32_t vsb = sb + VS_OFF + buf * 8192;

        if (kt < ktmax) { prefetch(kt + 1, buf ^ 1); CP_COMMIT(); }

        // ---- S = Q @ K^T ----
        float s[2][8][4];
#pragma unroll
        for (int mt = 0; mt < 2; mt++)
#pragma unroll
            for (int nf = 0; nf < 8; nf++)
#pragma unroll
                for (int e = 0; e < 4; e++) s[mt][nf][e] = 0.f;

#pragma unroll
        for (int kc = 0; kc < 4; kc++) {
            uint32_t kbf[4][4];
#pragma unroll
            for (int np = 0; np < 4; np++) {
                uint32_t off = (uint32_t)(np * 16 + bR8 + lr) * 128 + (kc * 2 + bCh) * 16;
                uint32_t sw = off ^ ((off >> 3) & 0x70);
                ldsm4(ksb + sw, kbf[np]);
            }
#pragma unroll
            for (int nf = 0; nf < 8; nf++) {
                uint32_t b0 = kbf[nf >> 1][(nf & 1) * 2];
                uint32_t b1 = kbf[nf >> 1][(nf & 1) * 2 + 1];
                mma16h(s[0][nf], qa[0][kc], b0, b1);
                mma16h(s[1][nf], qa[1][kc], b0, b1);
            }
        }

        // ---- causal mask on diagonal-straddling tiles ----
        if (kt >= 2 * qb) {
#pragma unroll
            for (int mt = 0; mt < 2; mt++) {
                int rb = qstart + warp * 32 + mt * 16 + g;
#pragma unroll
                for (int nf = 0; nf < 8; nf++) {
                    int c0 = kb + nf * 8 + 2 * t;
                    if (c0     > rb)     s[mt][nf][0] = -INFINITY;
                    if (c0 + 1 > rb)     s[mt][nf][1] = -INFINITY;
                    if (c0     > rb + 8) s[mt][nf][2] = -INFINITY;
                    if (c0 + 1 > rb + 8) s[mt][nf][3] = -INFINITY;
                }
            }
        }

        // ---- online softmax (exp2 domain; Q pre-scaled) ----
#pragma unroll
        for (int mt = 0; mt < 2; mt++) {
            float mx0 = -INFINITY, mx1 = -INFINITY;
#pragma unroll
            for (int nf = 0; nf < 8; nf++) {
                mx0 = fmaxf(mx0, fmaxf(s[mt][nf][0], s[mt][nf][1]));
                mx1 = fmaxf(mx1, fmaxf(s[mt][nf][2], s[mt][nf][3]));
            }
            mx0 = fmaxf(mx0, __shfl_xor_sync(0xffffffffu, mx0, 1));
            mx0 = fmaxf(mx0, __shfl_xor_sync(0xffffffffu, mx0, 2));
            mx1 = fmaxf(mx1, __shfl_xor_sync(0xffffffffu, mx1, 1));
            mx1 = fmaxf(mx1, __shfl_xor_sync(0xffffffffu, mx1, 2));

            float mn0 = fmaxf(mr[mt][0], mx0), mn1 = fmaxf(mr[mt][1], mx1);
            float corr0 = ex2f(mr[mt][0] - mn0), corr1 = ex2f(mr[mt][1] - mn1);
            float sum0 = 0.f, sum1 = 0.f;
#pragma unroll
            for (int nf = 0; nf < 8; nf++) {
                s[mt][nf][0] = ex2f(s[mt][nf][0] - mn0); sum0 += s[mt][nf][0];
                s[mt][nf][1] = ex2f(s[mt][nf][1] - mn0); sum0 += s[mt][nf][1];
                s[mt][nf][2] = ex2f(s[mt][nf][2] - mn1); sum1 += s[mt][nf][2];
                s[mt][nf][3] = ex2f(s[mt][nf][3] - mn1); sum1 += s[mt][nf][3];
            }
            sum0 += __shfl_xor_sync(0xffffffffu, sum0, 1);
            sum0 += __shfl_xor_sync(0xffffffffu, sum0, 2);
            sum1 += __shfl_xor_sync(0xffffffffu, sum1, 1);
            sum1 += __shfl_xor_sync(0xffffffffu, sum1, 2);

            lsum[mt][0] = lsum[mt][0] * corr0 + sum0;  mr[mt][0] = mn0;
            lsum[mt][1] = lsum[mt][1] * corr1 + sum1;  mr[mt][1] = mn1;
#pragma unroll
            for (int nf = 0; nf < 8; nf++) {
                o[mt][nf][0] *= corr0; o[mt][nf][1] *= corr0;
                o[mt][nf][2] *= corr1; o[mt][nf][3] *= corr1;
            }

            // store P as fp16 (warp-private rows, SW128 on 128B rows)
            int pr0 = warp * 32 + mt * 16 + g;
#pragma unroll
            for (int nf = 0; nf < 8; nf++) {
                int pc = nf * 8 + 2 * t;
                uint32_t o1 = (uint32_t)pr0 * 128 + pc * 2;
                uint32_t o2 = (uint32_t)(pr0 + 8) * 128 + pc * 2;
                *reinterpret_cast<__half2*>(fsm + PS_OFF + (o1 ^ ((o1 >> 3) & 0x70))) =
                    __floats2half2_rn(s[mt][nf][0], s[mt][nf][1]);
                *reinterpret_cast<__half2*>(fsm + PS_OFF + (o2 ^ ((o2 >> 3) & 0x70))) =
                    __floats2half2_rn(s[mt][nf][2], s[mt][nf][3]);
            }
        }
        __syncwarp();

        // ---- O += P @ V  (V^T in smem: [dim][tok], non-trans B pattern) ----
#pragma unroll
        for (int kc = 0; kc < 4; kc++) {
            uint32_t paf[2][4];
#pragma unroll
            for (int mt = 0; mt < 2; mt++) {
                uint32_t off = (uint32_t)(warp * 32 + mt * 16 + aR8 + lr) * 128 + (kc * 2 + aCh) * 16;
                uint32_t sw = off ^ ((off >> 3) & 0x70);
                ldsm4(sb + PS_OFF + sw, paf[mt]);
            }
            uint32_t vbf[4][4];
#pragma unroll
            for (int np = 0; np < 4; np++) {
                uint32_t off = (uint32_t)(np * 16 + bR8 + lr) * 128 + (kc * 2 + bCh) * 16;
                uint32_t sw = off ^ ((off >> 3) & 0x70);
                ldsm4(vsb + sw, vbf[np]);
            }
#pragma unroll
            for (int nf = 0; nf < 8; nf++) {
                uint32_t b0 = vbf[nf >> 1][(nf & 1) * 2];
                uint32_t b1 = vbf[nf >> 1][(nf & 1) * 2 + 1];
                mma16h(o[0][nf], paf[0], b0, b1);
                mma16h(o[1][nf], paf[1], b0, b1);
            }
        }

        if (kt < ktmax) CP_WAIT0();
        __syncthreads();
    }

    // ---- finalize: write bf16 hi/lo (feeds O projection) ----
#pragma unroll
    for (int mt = 0; mt < 2; mt++) {
        float inv0 = 1.0f / lsum[mt][0], inv1 = 1.0f / lsum[mt][1];
        int ro0 = rowbase + qstart + warp * 32 + mt * 16 + g;
#pragma unroll
        for (int nf = 0; nf < 8; nf++) {
            int colx = hoff + nf * 8 + 2 * t;
            float v00 = o[mt][nf][0] * inv0, v01 = o[mt][nf][1] * inv0;
            float v10 = o[mt][nf][2] * inv1, v11 = o[mt][nf][3] * inv1;
            __nv_bfloat16 h00 = __float2bfloat16(v00), h01 = __float2bfloat16(v01);
            __nv_bfloat16 h10 = __float2bfloat16(v10), h11 = __float2bfloat16(v11);
            *reinterpret_cast<__nv_bfloat162*>(&Ohi[(size_t)ro0 * D_MODEL + colx]) =
                __halves2bfloat162(h00, h01);
            *reinterpret_cast<__nv_bfloat162*>(&Ohi[(size_t)(ro0 + 8) * D_MODEL + colx]) =
                __halves2bfloat162(h10, h11);
            __nv_bfloat16 l00 = __float2bfloat16(v00 - __bfloat162float(h00));
            __nv_bfloat16 l01 = __float2bfloat16(v01 - __bfloat162float(h01));
            __nv_bfloat16 l10 = __float2bfloat16(v10 - __bfloat162float(h10));
            __nv_bfloat16 l11 = __float2bfloat16(v11 - __bfloat162float(h11));
            *reinterpret_cast<__nv_bfloat162*>(&Olo[(size_t)ro0 * D_MODEL + colx]) =
                __halves2bfloat162(l00, l01);
            *reinterpret_cast<__nv_bfloat162*>(&Olo[(size_t)(ro0 + 8) * D_MODEL + colx]) =
                __halves2bfloat162(l10, l11);
        }
    }
}

// ---------------------------------------------------------------------------
// Launch
// ---------------------------------------------------------------------------
extern "C" void kernel_launch(void* const* d_in, const int* in_sizes, int n_in,
                              void* d_out, int out_size)
{
    const float* x  = (const float*)d_in[0];
    const float* Wq = (const float*)d_in[1];
    const float* bq = (const float*)d_in[2];
    const float* Wk = (const float*)d_in[3];
    const float* bk = (const float*)d_in[4];
    const float* Wv = (const float*)d_in[5];
    const float* bv = (const float*)d_in[6];
    const float* Wo = (const float*)d_in[7];
    const float* bo = (const float*)d_in[8];
    float* out = (float*)d_out;

    __half *Qh, *Kh, *Vt;
    __nv_bfloat16 *xhi, *xlo, *ohi, *olo, *whi, *wlo;
    cudaGetSymbolAddress((void**)&Qh, g_Qh);
    cudaGetSymbolAddress((void**)&Kh, g_Kh);
    cudaGetSymbolAddress((void**)&Vt, g_Vt);
    cudaGetSymbolAddress((void**)&xhi, g_xhi);
    cudaGetSymbolAddress((void**)&xlo, g_xlo);
    cudaGetSymbolAddress((void**)&ohi, g_ohi);
    cudaGetSymbolAddress((void**)&olo, g_olo);
    cudaGetSymbolAddress((void**)&whi, g_whi);
    cudaGetSymbolAddress((void**)&wlo, g_wlo);

    cudaFuncSetAttribute(gemm_bf16x2, cudaFuncAttributeMaxDynamicSharedMemorySize, G_SMEM);
    cudaFuncSetAttribute(flash_h, cudaFuncAttributeMaxDynamicSharedMemorySize, FL_SMEM);

    const size_t wstep = (size_t)D_MODEL * D_MODEL;
    const int n4total = N4_X + 4 * N4_W;

    split_all<<<n4total / 256, 256>>>(x, Wq, Wk, Wv, Wo, xhi, xlo, whi, wlo);

    dim3 qkvgrid(D_MODEL / 128, M_ROWS / 128, 3);
    gemm_bf16x2<<<qkvgrid, 256, G_SMEM>>>(xhi, xlo, whi, wlo, bq, bk, bv,
                                          1, Qh, Kh, Vt, nullptr);

    dim3 fgrid(T_SEQ / 128, B_SZ * N_HEADS);
    flash_h<<<fgrid, 128, FL_SMEM>>>(Qh, Kh, Vt, ohi, olo);

    dim3 ogrid(D_MODEL / 128, M_ROWS / 128, 1);
    gemm_bf16x2<<<ogrid, 256, G_SMEM>>>(ohi, olo, whi + 3 * wstep, wlo + 3 * wstep,
                                        bo, bo, bo, 0, nullptr, nullptr, nullptr, out);
}